// round 6
// baseline (speedup 1.0000x reference)
#include <cuda_runtime.h>
#include <cuda_bf16.h>

#define NN 20000
#define NE 100000

typedef unsigned long long ull;

__device__ float g_ebn[NE * 10];
__device__ float g_h1[NE * 16];
__device__ float g_h2[NE * 32];
__device__ float g_xbn[NN * 16];
__device__ float g_x1[NN * 32];
__device__ float g_x2[NN * 64];
__device__ float g_m1[NE * 64];            // edge-MLP layer1 activations
__device__ float g_wT1[2 * 16 * 32 * 8];   // conv1 weights [ic2][j16][o32][il8]
__device__ float g_wT2[2 * 8 * 2 * 16 * 32 * 4]; // conv2 [oh2][ic8][jh2][jl16][o32][il4]
__device__ double g_dsum[26], g_dss[26];
__device__ float g_emean[10], g_ers[10];
__device__ float g_xmean[16], g_xrs[16];

__device__ __forceinline__ float lrelu(float v) { return v > 0.f ? v : 0.1f * v; }

// ---- packed f32x2 helpers (sm_103a FFMA2) -----------------------------------
__device__ __forceinline__ ull bcast2(float v) {
    ull r;
    unsigned u = __float_as_uint(v);
    asm("mov.b64 %0, {%1, %2};" : "=l"(r) : "r"(u), "r"(u));
    return r;
}
__device__ __forceinline__ ull fma2(ull a, ull b, ull c) {
    ull d;
    asm("fma.rn.f32x2 %0, %1, %2, %3;" : "=l"(d) : "l"(a), "l"(b), "l"(c));
    return d;
}
__device__ __forceinline__ float2 unpk2(ull v) {
    unsigned lo, hi;
    asm("mov.b64 {%0, %1}, %2;" : "=r"(lo), "=r"(hi) : "l"(v));
    return make_float2(__uint_as_float(lo), __uint_as_float(hi));
}

// ---- cp.async helpers -------------------------------------------------------
__device__ __forceinline__ void cp16(unsigned dst, const float* src) {
    asm volatile("cp.async.cg.shared.global [%0], [%1], 16;\n" :: "r"(dst), "l"(src));
}
#define CP_COMMIT() asm volatile("cp.async.commit_group;\n" ::: "memory")
#define CP_WAIT1()  asm volatile("cp.async.wait_group 1;\n" ::: "memory")

// ---------------- BatchNorm statistics (correct column-fixed scheme) ---------
__global__ void bn_init() {
    int t = threadIdx.x;
    if (t < 26) { g_dsum[t] = 0.0; g_dss[t] = 0.0; }
}

// blocks 0..39: edge col c=b%10, row chunk b/10 (4 chunks x 25000 rows)
// blocks 40..55: node col c=b-40, all 20000 rows
__global__ void bn_acc(const float* __restrict__ e, const float* __restrict__ x) {
    __shared__ double s_sh[256], ss_sh[256];
    int b = blockIdx.x, tid = threadIdx.x;
    double s = 0.0, ss = 0.0;
    int slot;
    if (b < 40) {
        int c = b % 10;
        int r0 = (b / 10) * 25000;
        for (int r = r0 + tid; r < r0 + 25000; r += 256) {
            float f = e[(size_t)r * 10 + c];
            s += (double)f; ss += (double)f * f;
        }
        slot = c;
    } else {
        int c = b - 40;
        for (int r = tid; r < NN; r += 256) {
            float f = x[(size_t)r * 16 + c];
            s += (double)f; ss += (double)f * f;
        }
        slot = 10 + c;
    }
    s_sh[tid] = s; ss_sh[tid] = ss;
    __syncthreads();
    for (int off = 128; off > 0; off >>= 1) {
        if (tid < off) { s_sh[tid] += s_sh[tid + off]; ss_sh[tid] += ss_sh[tid + off]; }
        __syncthreads();
    }
    if (tid == 0) {
        atomicAdd(&g_dsum[slot], s_sh[0]);
        atomicAdd(&g_dss[slot], ss_sh[0]);
    }
}

__global__ void bn_fin() {
    int t = threadIdx.x;
    if (t < 10) {
        double m = g_dsum[t] / NE;
        double var = g_dss[t] / NE - m * m;
        g_emean[t] = (float)m;
        g_ers[t] = (float)(1.0 / sqrt(var + 1e-5));
    } else if (t < 26) {
        double m = g_dsum[t] / NN;
        double var = g_dss[t] / NN - m * m;
        g_xmean[t - 10] = (float)m;
        g_xrs[t - 10] = (float)(1.0 / sqrt(var + 1e-5));
    }
}

// ---------------- weight transposes (merged) ---------------------------------
__global__ void prep_w(const float* __restrict__ w1g, const float* __restrict__ w2g) {
    int b = blockIdx.x;
    if (b < 32) {  // nn1_w2 [16,512] -> [ic2][j16][o32][il8]
        int idx = b * 256 + threadIdx.x;
        int il = idx & 7, o = (idx >> 3) & 31, j = (idx >> 8) & 15, ic = (idx >> 12) & 1;
        g_wT1[((ic * 16 + j) * 32 + o) * 8 + il] = w1g[j * 512 + (ic * 8 + il) * 32 + o];
    } else {       // nn2_w2 [32,2048] -> [oh2][ic8][jh2][jl16][o32][il4]
        int idx = (b - 32) * 256 + threadIdx.x;
        int il = idx & 3, o = (idx >> 2) & 31, jl = (idx >> 7) & 15,
            jh = (idx >> 11) & 1, ic = (idx >> 12) & 7, oh = (idx >> 15) & 1;
        g_wT2[idx] = w2g[(jh * 16 + jl) * 2048 + (ic * 4 + il) * 64 + oh * 32 + o];
    }
}

// ---------------- K1: edge BN + h1 + h2 --------------------------------------
__global__ void k1_edge(const float* __restrict__ e,
                        const float* __restrict__ eg, const float* __restrict__ eb,
                        const float* __restrict__ w1, const float* __restrict__ b1,
                        const float* __restrict__ w2, const float* __restrict__ b2) {
    __shared__ float sw1[160], sw2[320], sb1[16], sb2[32], sg[10], sb[10], sm[10], srs[10];
    int tid = threadIdx.x;
    for (int i = tid; i < 160; i += 256) sw1[i] = w1[i];
    for (int i = tid; i < 320; i += 256) sw2[i] = w2[i];
    if (tid < 16) sb1[tid] = b1[tid];
    if (tid < 32) sb2[tid] = b2[tid];
    if (tid < 10) { sg[tid] = eg[tid]; sb[tid] = eb[tid]; sm[tid] = g_emean[tid]; srs[tid] = g_ers[tid]; }
    __syncthreads();
    int eid = blockIdx.x * 256 + tid;
    if (eid >= NE) return;
    float ev[10];
#pragma unroll
    for (int c = 0; c < 10; c++) {
        float f = (e[eid * 10 + c] - sm[c]) * srs[c] * sg[c] + sb[c];
        ev[c] = f;
        g_ebn[eid * 10 + c] = f;
    }
#pragma unroll
    for (int o = 0; o < 16; o++) {
        float t = sb1[o];
#pragma unroll
        for (int c = 0; c < 10; c++) t += ev[c] * sw1[c * 16 + o];
        g_h1[eid * 16 + o] = lrelu(t);
    }
#pragma unroll
    for (int o = 0; o < 32; o++) {
        float t = sb2[o];
#pragma unroll
        for (int c = 0; c < 10; c++) t += ev[c] * sw2[c * 32 + o];
        g_h2[eid * 32 + o] = lrelu(t);
    }
}

// ---------------- K2: node BN + x1 = xbn @ l1_root + l1_bias -----------------
__global__ void k2_node(const float* __restrict__ x,
                        const float* __restrict__ ng, const float* __restrict__ nb,
                        const float* __restrict__ root, const float* __restrict__ bias) {
    __shared__ float sroot[512], sbias[32], sg[16], sb[16], sm[16], srs[16];
    int tid = threadIdx.x;
    for (int i = tid; i < 512; i += 128) sroot[i] = root[i];
    if (tid < 32) sbias[tid] = bias[tid];
    if (tid < 16) { sg[tid] = ng[tid]; sb[tid] = nb[tid]; sm[tid] = g_xmean[tid]; srs[tid] = g_xrs[tid]; }
    __syncthreads();
    int nid = blockIdx.x * 128 + tid;
    if (nid >= NN) return;
    float xv[16];
#pragma unroll
    for (int i = 0; i < 16; i++) {
        float f = (x[nid * 16 + i] - sm[i]) * srs[i] * sg[i] + sb[i];
        xv[i] = f;
        g_xbn[nid * 16 + i] = f;
    }
#pragma unroll
    for (int o = 0; o < 32; o++) {
        float t = sbias[o];
#pragma unroll
        for (int i = 0; i < 16; i++) t += xv[i] * sroot[i * 32 + o];
        g_x1[nid * 32 + o] = t;
    }
}

// ---------------- K3: NNConv1 message + scatter (FFMA2) ----------------------
__global__ __launch_bounds__(256) void k3_conv1(const int* __restrict__ ei,
                                                const float* __restrict__ b2) {
    __shared__ __align__(16) float swT[8192];     // 2*16*32*8
    __shared__ __align__(16) float h_sh[16 * 68];
    __shared__ __align__(16) float x_sh[64 * 16];
    __shared__ int dst_sh[64];
    int tid = threadIdx.x;
    int e0 = blockIdx.x * 64;
    for (int i = tid; i < 8192; i += 256) swT[i] = g_wT1[i];
    if (tid < 64) {
        int ge = e0 + tid;
        dst_sh[tid] = (ge < NE) ? ei[NE + ge] : 0;
    }
    for (int i = tid; i < 1024; i += 256) {
        int el = i >> 4, j = i & 15;
        int ge = e0 + el;
        h_sh[j * 68 + el] = (ge < NE) ? g_h1[ge * 16 + j] : 0.f;
    }
    for (int i = tid; i < 1024; i += 256) {
        int el = i >> 4, ii = i & 15;
        int ge = e0 + el;
        x_sh[el * 16 + ii] = (ge < NE) ? g_xbn[ei[ge] * 16 + ii] : 0.f;
    }
    __syncthreads();

    int o = tid & 31;
    int w = tid >> 5;
    float acc[8];
#pragma unroll
    for (int eL = 0; eL < 8; eL++) acc[eL] = 0.f;

#pragma unroll
    for (int ic = 0; ic < 2; ic++) {
        ull t2[4][8];
#pragma unroll
        for (int il = 0; il < 8; il++) {
            ull bp = bcast2(b2[(ic * 8 + il) * 32 + o]);
#pragma unroll
            for (int p = 0; p < 4; p++) t2[p][il] = bp;
        }

#pragma unroll 4
        for (int j = 0; j < 16; j++) {
            const ull* hp = (const ull*)&h_sh[j * 68 + w * 8];
            ulonglong2 hA = *(const ulonglong2*)hp;
            ulonglong2 hB = *(const ulonglong2*)(hp + 2);
            ull hv2[4] = {hA.x, hA.y, hB.x, hB.y};
            const float* wp = &swT[((ic * 16 + j) * 32 + o) * 8];
            float4 wa = *(const float4*)wp;
            float4 wb = *(const float4*)(wp + 4);
            ull w2[8] = {bcast2(wa.x), bcast2(wa.y), bcast2(wa.z), bcast2(wa.w),
                         bcast2(wb.x), bcast2(wb.y), bcast2(wb.z), bcast2(wb.w)};
#pragma unroll
            for (int p = 0; p < 4; p++)
#pragma unroll
                for (int il = 0; il < 8; il++) t2[p][il] = fma2(hv2[p], w2[il], t2[p][il]);
        }
#pragma unroll
        for (int p = 0; p < 4; p++)
#pragma unroll
            for (int il = 0; il < 8; il++) {
                float2 v = unpk2(t2[p][il]);
                acc[2 * p]     += x_sh[(w * 8 + 2 * p) * 16 + ic * 8 + il] * lrelu(v.x);
                acc[2 * p + 1] += x_sh[(w * 8 + 2 * p + 1) * 16 + ic * 8 + il] * lrelu(v.y);
            }
    }
#pragma unroll
    for (int eL = 0; eL < 8; eL++) {
        int ge = e0 + w * 8 + eL;
        if (ge < NE) atomicAdd(&g_x1[dst_sh[w * 8 + eL] * 32 + o], acc[eL]);
    }
}

// ---------------- K4: x2 = x1 @ l2_root + l2_bias ----------------------------
__global__ void k4_node(const float* __restrict__ root, const float* __restrict__ bias) {
    __shared__ float sroot[2048], sbias[64];
    int tid = threadIdx.x;
    for (int i = tid; i < 2048; i += 256) sroot[i] = root[i];
    if (tid < 64) sbias[tid] = bias[tid];
    __syncthreads();
    int idx = blockIdx.x * 256 + tid;
    if (idx >= NN * 64) return;
    int n = idx >> 6, o = idx & 63;
    float t = sbias[o];
#pragma unroll
    for (int i = 0; i < 32; i++) t += g_x1[n * 32 + i] * sroot[i * 64 + o];
    g_x2[idx] = t;
}

// ---------------- K5: NNConv2 (dominant): 64 edges/block, o-split, cp.async --
__global__ __launch_bounds__(256, 2) void k5_conv2(const int* __restrict__ ei,
                                                   const float* __restrict__ b2) {
    __shared__ __align__(16) float wbuf[2][2048];  // 2 x 8KB
    __shared__ __align__(16) float h_sh[32 * 64];  // [j][e]
    __shared__ __align__(16) float x_sh[64 * 32];  // [e][i]
    __shared__ int dst_sh[64];
    int tid = threadIdx.x;
    int oh = blockIdx.x & 1;
    int e0 = (blockIdx.x >> 1) * 64;
    const float* wbase = g_wT2 + oh * 16 * 2048;

    // prefetch chunks 0,1
    {
        unsigned d0 = (unsigned)__cvta_generic_to_shared(&wbuf[0][tid * 8]);
        cp16(d0, wbase + tid * 8);
        cp16(d0 + 16, wbase + tid * 8 + 4);
        CP_COMMIT();
        unsigned d1 = (unsigned)__cvta_generic_to_shared(&wbuf[1][tid * 8]);
        cp16(d1, wbase + 2048 + tid * 8);
        cp16(d1 + 16, wbase + 2048 + tid * 8 + 4);
        CP_COMMIT();
    }

    if (tid < 64) {
        int ge = e0 + tid;
        dst_sh[tid] = (ge < NE) ? ei[NE + ge] : 0;
    }
    for (int i = tid; i < 2048; i += 256) {
        int el = i >> 5, j = i & 31;
        int ge = e0 + el;
        h_sh[j * 64 + el] = (ge < NE) ? g_h2[ge * 32 + j] : 0.f;
    }
    for (int i = tid; i < 2048; i += 256) {
        int el = i >> 5, ii = i & 31;
        int ge = e0 + el;
        x_sh[el * 32 + ii] = (ge < NE) ? g_x1[ei[ge] * 32 + ii] : 0.f;
    }

    int o = tid & 31;
    int g = tid >> 5;
    float acc[8];
#pragma unroll
    for (int eL = 0; eL < 8; eL++) acc[eL] = 0.f;
    ull t2[4][4];

#pragma unroll 1
    for (int c = 0; c < 16; c++) {
        int ic = c >> 1, jh = c & 1;
        CP_WAIT1();
        __syncthreads();           // buffer c&1 ready + (c==0) h/x staging done
        const float* wc = wbuf[c & 1];

        if (jh == 0) {
#pragma unroll
            for (int il = 0; il < 4; il++) {
                ull bp = bcast2(b2[(ic * 4 + il) * 64 + oh * 32 + o]);
#pragma unroll
                for (int p = 0; p < 4; p++) t2[p][il] = bp;
            }
        }

#pragma unroll 4
        for (int jl = 0; jl < 16; jl++) {
            const ull* hp = (const ull*)&h_sh[((jh << 4) + jl) * 64 + g * 8];
            ulonglong2 hA = *(const ulonglong2*)hp;
            ulonglong2 hB = *(const ulonglong2*)(hp + 2);
            ull hv2[4] = {hA.x, hA.y, hB.x, hB.y};
            float4 wv = *(const float4*)&wc[(jl * 32 + o) * 4];
            ull w2[4] = {bcast2(wv.x), bcast2(wv.y), bcast2(wv.z), bcast2(wv.w)};
#pragma unroll
            for (int p = 0; p < 4; p++)
#pragma unroll
                for (int il = 0; il < 4; il++) t2[p][il] = fma2(hv2[p], w2[il], t2[p][il]);
        }

        if (jh == 1) {
#pragma unroll
            for (int p = 0; p < 4; p++)
#pragma unroll
                for (int il = 0; il < 4; il++) {
                    float2 v = unpk2(t2[p][il]);
                    acc[2 * p]     += x_sh[(g * 8 + 2 * p) * 32 + ic * 4 + il] * lrelu(v.x);
                    acc[2 * p + 1] += x_sh[(g * 8 + 2 * p + 1) * 32 + ic * 4 + il] * lrelu(v.y);
                }
        }
        __syncthreads();           // everyone done reading buffer c&1
        if (c + 2 < 16) {
            unsigned d = (unsigned)__cvta_generic_to_shared(&wbuf[c & 1][tid * 8]);
            const float* src = wbase + (c + 2) * 2048 + tid * 8;
            cp16(d, src);
            cp16(d + 16, src + 4);
            CP_COMMIT();
        }
    }

#pragma unroll
    for (int eL = 0; eL < 8; eL++) {
        int ge = e0 + g * 8 + eL;
        if (ge < NE)
            atomicAdd(&g_x2[dst_sh[g * 8 + eL] * 64 + oh * 32 + o], acc[eL]);
    }
}

// ---------------- K6a: edge MLP layer1 (138 -> 64), o-split, FFMA2 -----------
__global__ __launch_bounds__(256) void k6a_mlp1(const int* __restrict__ ei,
                                                const float* __restrict__ w1,
                                                const float* __restrict__ b1) {
    __shared__ float sw1[138 * 32];                 // 17.25KB (one o-half)
    __shared__ __align__(16) float in_sh[138 * 32]; // [k][e]
    int tid = threadIdx.x;
    int oh = blockIdx.x & 1;
    int e0 = (blockIdx.x >> 1) * 32;

    for (int i = tid; i < 138 * 32; i += 256) {
        int k = i >> 5, ol = i & 31;
        sw1[i] = w1[k * 64 + oh * 32 + ol];
    }
    for (int i = tid; i < 138 * 32; i += 256) {
        int e = i & 31, k = i >> 5;
        float v;
        if (k < 64)       v = g_x2[ei[e0 + e] * 64 + k];
        else if (k < 128) v = g_x2[ei[NE + e0 + e] * 64 + (k - 64)];
        else              v = g_ebn[(e0 + e) * 10 + (k - 128)];
        in_sh[k * 32 + e] = v;
    }
    __syncthreads();

    int o = tid & 31, g = tid >> 5;
    ull a0 = bcast2(b1[oh * 32 + o]);
    ull a1 = a0;
#pragma unroll 2
    for (int k = 0; k < 138; k++) {
        ull wb = bcast2(sw1[k * 32 + o]);
        ulonglong2 h = *(const ulonglong2*)&in_sh[k * 32 + g * 4];
        a0 = fma2(h.x, wb, a0);
        a1 = fma2(h.y, wb, a1);
    }
    float2 v0 = unpk2(a0), v1 = unpk2(a1);
    int ob = oh * 32 + o;
    g_m1[(e0 + g * 4 + 0) * 64 + ob] = lrelu(v0.x);
    g_m1[(e0 + g * 4 + 1) * 64 + ob] = lrelu(v0.y);
    g_m1[(e0 + g * 4 + 2) * 64 + ob] = lrelu(v1.x);
    g_m1[(e0 + g * 4 + 3) * 64 + ob] = lrelu(v1.y);
}

// ---------------- K6b: edge MLP layers 2-5 -----------------------------------
__global__ __launch_bounds__(256) void k6b_mlp(
    const float* __restrict__ w2, const float* __restrict__ b2,
    const float* __restrict__ w3, const float* __restrict__ b3,
    const float* __restrict__ w4, const float* __restrict__ b4,
    const float* __restrict__ w5, const float* __restrict__ b5,
    float* __restrict__ out) {
    __shared__ float sw2[2048], sw3[512], sw4[128], sw5[16];
    __shared__ float sb2[32], sb3[16], sb4[8], sb5[2];
    __shared__ __align__(16) float h1_sh[64 * 36];
    __shared__ __align__(16) float h2_sh[32 * 36];
    int tid = threadIdx.x;
    int e0 = blockIdx.x * 32;

    for (int i = tid; i < 2048; i += 256) sw2[i] = w2[i];
    for (int i = tid; i < 512; i += 256) sw3[i] = w3[i];
    if (tid < 128) sw4[tid] = w4[tid];
    if (tid < 16) sw5[tid] = w5[tid];
    if (tid < 32) sb2[tid] = b2[tid];
    if (tid < 16) sb3[tid] = b3[tid];
    if (tid < 8) sb4[tid] = b4[tid];
    if (tid < 2) sb5[tid] = b5[tid];
    for (int i = tid; i < 2048; i += 256) {
        int e = i & 31, k = i >> 5;
        h1_sh[k * 36 + e] = g_m1[(e0 + e) * 64 + k];
    }
    __syncthreads();

    // layer 2: 64 -> 32 (FFMA2)
    {
        int o = tid & 31, g = tid >> 5;
        ull a0 = bcast2(sb2[o]);
        ull a1 = a0;
#pragma unroll 4
        for (int k = 0; k < 64; k++) {
            ull wb = bcast2(sw2[k * 32 + o]);
            ulonglong2 h = *(const ulonglong2*)&h1_sh[k * 36 + g * 4];
            a0 = fma2(h.x, wb, a0);
            a1 = fma2(h.y, wb, a1);
        }
        float2 v0 = unpk2(a0), v1 = unpk2(a1);
        h2_sh[o * 36 + g * 4 + 0] = lrelu(v0.x);
        h2_sh[o * 36 + g * 4 + 1] = lrelu(v0.y);
        h2_sh[o * 36 + g * 4 + 2] = lrelu(v1.x);
        h2_sh[o * 36 + g * 4 + 3] = lrelu(v1.y);
    }
    __syncthreads();

    // layers 3-5: one thread per edge
    if (tid < 32) {
        int e = tid, ge = e0 + e;
        float h2r[32];
#pragma unroll
        for (int k = 0; k < 32; k++) h2r[k] = h2_sh[k * 36 + e];
        float h3[16];
#pragma unroll
        for (int o = 0; o < 16; o++) {
            float a = sb3[o];
#pragma unroll
            for (int k = 0; k < 32; k++) a += h2r[k] * sw3[k * 16 + o];
            h3[o] = lrelu(a);
        }
        float h4[8];
#pragma unroll
        for (int o = 0; o < 8; o++) {
            float a = sb4[o];
#pragma unroll
            for (int k = 0; k < 16; k++) a += h3[k] * sw4[k * 8 + o];
            h4[o] = lrelu(a);
        }
#pragma unroll
        for (int o = 0; o < 2; o++) {
            float a = sb5[o];
#pragma unroll
            for (int k = 0; k < 8; k++) a += h4[k] * sw5[k * 2 + o];
            out[(size_t)ge * 2 + o] = a;
        }
    }
}

// ---------------- launch -----------------------------------------------------
extern "C" void kernel_launch(void* const* d_in, const int* in_sizes, int n_in,
                              void* d_out, int out_size) {
    const float* x = (const float*)d_in[0];
    const float* e = (const float*)d_in[1];
    const int* ei = (const int*)d_in[2];     // edge_index: int32
    // d_in[3] xbatch unused
    const float* bn_node_g = (const float*)d_in[4];
    const float* bn_node_b = (const float*)d_in[5];
    const float* bn_edge_g = (const float*)d_in[6];
    const float* bn_edge_b = (const float*)d_in[7];
    const float* nn1_w1 = (const float*)d_in[8];
    const float* nn1_b1 = (const float*)d_in[9];
    const float* nn1_w2 = (const float*)d_in[10];
    const float* nn1_b2 = (const float*)d_in[11];
    const float* nn2_w1 = (const float*)d_in[12];
    const float* nn2_b1 = (const float*)d_in[13];
    const float* nn2_w2 = (const float*)d_in[14];
    const float* nn2_b2 = (const float*)d_in[15];
    const float* l1_root = (const float*)d_in[16];
    const float* l1_bias = (const float*)d_in[17];
    const float* l2_root = (const float*)d_in[18];
    const float* l2_bias = (const float*)d_in[19];
    const float* mlp_w1 = (const float*)d_in[20];
    const float* mlp_b1 = (const float*)d_in[21];
    const float* mlp_w2 = (const float*)d_in[22];
    const float* mlp_b2 = (const float*)d_in[23];
    const float* mlp_w3 = (const float*)d_in[24];
    const float* mlp_b3 = (const float*)d_in[25];
    const float* mlp_w4 = (const float*)d_in[26];
    const float* mlp_b4 = (const float*)d_in[27];
    const float* mlp_w5 = (const float*)d_in[28];
    const float* mlp_b5 = (const float*)d_in[29];
    float* out = (float*)d_out;

    bn_init<<<1, 32>>>();
    bn_acc<<<56, 256>>>(e, x);
    bn_fin<<<1, 32>>>();
    prep_w<<<288, 256>>>(nn1_w2, nn2_w2);
    k1_edge<<<(NE + 255) / 256, 256>>>(e, bn_edge_g, bn_edge_b, nn1_w1, nn1_b1, nn2_w1, nn2_b1);
    k2_node<<<(NN + 127) / 128, 128>>>(x, bn_node_g, bn_node_b, l1_root, l1_bias);
    k3_conv1<<<(NE + 63) / 64, 256>>>(ei, nn1_b2);
    k4_node<<<(NN * 64 + 255) / 256, 256>>>(l2_root, l2_bias);
    k5_conv2<<<((NE + 63) / 64) * 2, 256>>>(ei, nn2_b2);
    k6a_mlp1<<<(NE / 32) * 2, 256>>>(ei, mlp_w1, mlp_b1);
    k6b_mlp<<<NE / 32, 256>>>(mlp_w2, mlp_b2, mlp_w3, mlp_b3,
                              mlp_w4, mlp_b4, mlp_w5, mlp_b5, out);
}

// round 7
// speedup vs baseline: 1.5623x; 1.5623x over previous
#include <cuda_runtime.h>
#include <cuda_bf16.h>

#define NN 20000
#define NE 100000

typedef unsigned long long ull;

__device__ float g_ebn[NE * 10];
__device__ float g_h1[NE * 16];
__device__ float g_h2[NE * 32];
__device__ float g_xbn[NN * 16];
__device__ float g_x1[NN * 32];
__device__ float g_x2[NN * 64];
__device__ float g_m1[NE * 64];            // edge-MLP layer1 activations
__device__ float g_wT1[2 * 16 * 32 * 8];   // conv1 weights [ic2][j16][o32][il8]
__device__ float g_wT2[8 * 32 * 64 * 4];   // conv2 weights [ic8][j32][o64][il4]
__device__ float g_emean[10], g_ers[10];
__device__ float g_xmean[16], g_xrs[16];

__device__ __forceinline__ float lrelu(float v) { return v > 0.f ? v : 0.1f * v; }

// ---- packed f32x2 helpers (sm_103a FFMA2) -----------------------------------
__device__ __forceinline__ ull bcast2(float v) {
    ull r;
    unsigned u = __float_as_uint(v);
    asm("mov.b64 %0, {%1, %2};" : "=l"(r) : "r"(u), "r"(u));
    return r;
}
__device__ __forceinline__ ull fma2(ull a, ull b, ull c) {
    ull d;
    asm("fma.rn.f32x2 %0, %1, %2, %3;" : "=l"(d) : "l"(a), "l"(b), "l"(c));
    return d;
}
__device__ __forceinline__ float2 unpk2(ull v) {
    unsigned lo, hi;
    asm("mov.b64 {%0, %1}, %2;" : "=r"(lo), "=r"(hi) : "l"(v));
    return make_float2(__uint_as_float(lo), __uint_as_float(hi));
}

// ---------------- BatchNorm statistics (biased var, eps=1e-5) ----------------
__device__ void bn_stats_impl(const float* __restrict__ v, int rows, int cols, int c,
                              float* mean_out, float* rs_out) {
    int tid = threadIdx.x;
    double s = 0.0, ss = 0.0;
    for (int r = tid; r < rows; r += blockDim.x) {
        float f = v[(size_t)r * cols + c];
        s += (double)f;
        ss += (double)f * (double)f;
    }
    __shared__ double sh[256];
    sh[tid] = s; __syncthreads();
    for (int off = 128; off > 0; off >>= 1) { if (tid < off) sh[tid] += sh[tid + off]; __syncthreads(); }
    double stot = sh[0]; __syncthreads();
    sh[tid] = ss; __syncthreads();
    for (int off = 128; off > 0; off >>= 1) { if (tid < off) sh[tid] += sh[tid + off]; __syncthreads(); }
    if (tid == 0) {
        double m = stot / rows;
        double var = sh[0] / rows - m * m;
        mean_out[c] = (float)m;
        rs_out[c] = (float)(1.0 / sqrt(var + 1e-5));
    }
}

__global__ void bn_stats_all(const float* __restrict__ e, const float* __restrict__ x) {
    if (blockIdx.x < 10) bn_stats_impl(e, NE, 10, blockIdx.x, g_emean, g_ers);
    else                 bn_stats_impl(x, NN, 16, blockIdx.x - 10, g_xmean, g_xrs);
}

// ---------------- weight transposes (merged) ---------------------------------
__global__ void prep_w(const float* __restrict__ w1g, const float* __restrict__ w2g) {
    int b = blockIdx.x;
    if (b < 32) {  // nn1_w2 [16,512] -> [ic2][j16][o32][il8]
        int idx = b * 256 + threadIdx.x;
        int il = idx & 7, o = (idx >> 3) & 31, j = (idx >> 8) & 15, ic = (idx >> 12) & 1;
        g_wT1[((ic * 16 + j) * 32 + o) * 8 + il] = w1g[j * 512 + (ic * 8 + il) * 32 + o];
    } else {       // nn2_w2 [32,2048] -> [ic8][j32][o64][il4]
        int idx = (b - 32) * 256 + threadIdx.x;
        int il = idx & 3, o = (idx >> 2) & 63, j = (idx >> 8) & 31, ic = (idx >> 13) & 7;
        g_wT2[((ic * 32 + j) * 64 + o) * 4 + il] = w2g[j * 2048 + (ic * 4 + il) * 64 + o];
    }
}

// ---------------- K1: edge BN + h1 + h2 --------------------------------------
__global__ void k1_edge(const float* __restrict__ e,
                        const float* __restrict__ eg, const float* __restrict__ eb,
                        const float* __restrict__ w1, const float* __restrict__ b1,
                        const float* __restrict__ w2, const float* __restrict__ b2) {
    __shared__ float sw1[160], sw2[320], sb1[16], sb2[32], sg[10], sb[10], sm[10], srs[10];
    int tid = threadIdx.x;
    for (int i = tid; i < 160; i += 256) sw1[i] = w1[i];
    for (int i = tid; i < 320; i += 256) sw2[i] = w2[i];
    if (tid < 16) sb1[tid] = b1[tid];
    if (tid < 32) sb2[tid] = b2[tid];
    if (tid < 10) { sg[tid] = eg[tid]; sb[tid] = eb[tid]; sm[tid] = g_emean[tid]; srs[tid] = g_ers[tid]; }
    __syncthreads();
    int eid = blockIdx.x * 256 + tid;
    if (eid >= NE) return;
    float ev[10];
#pragma unroll
    for (int c = 0; c < 10; c++) {
        float f = (e[eid * 10 + c] - sm[c]) * srs[c] * sg[c] + sb[c];
        ev[c] = f;
        g_ebn[eid * 10 + c] = f;
    }
#pragma unroll
    for (int o = 0; o < 16; o++) {
        float t = sb1[o];
#pragma unroll
        for (int c = 0; c < 10; c++) t += ev[c] * sw1[c * 16 + o];
        g_h1[eid * 16 + o] = lrelu(t);
    }
#pragma unroll
    for (int o = 0; o < 32; o++) {
        float t = sb2[o];
#pragma unroll
        for (int c = 0; c < 10; c++) t += ev[c] * sw2[c * 32 + o];
        g_h2[eid * 32 + o] = lrelu(t);
    }
}

// ---------------- K2: node BN + x1 = xbn @ l1_root + l1_bias -----------------
__global__ void k2_node(const float* __restrict__ x,
                        const float* __restrict__ ng, const float* __restrict__ nb,
                        const float* __restrict__ root, const float* __restrict__ bias) {
    __shared__ float sroot[512], sbias[32], sg[16], sb[16], sm[16], srs[16];
    int tid = threadIdx.x;
    for (int i = tid; i < 512; i += 256) sroot[i] = root[i];
    if (tid < 32) sbias[tid] = bias[tid];
    if (tid < 16) { sg[tid] = ng[tid]; sb[tid] = nb[tid]; sm[tid] = g_xmean[tid]; srs[tid] = g_xrs[tid]; }
    __syncthreads();
    int nid = blockIdx.x * 256 + tid;
    if (nid >= NN) return;
    float xv[16];
#pragma unroll
    for (int i = 0; i < 16; i++) {
        float f = (x[nid * 16 + i] - sm[i]) * srs[i] * sg[i] + sb[i];
        xv[i] = f;
        g_xbn[nid * 16 + i] = f;
    }
#pragma unroll
    for (int o = 0; o < 32; o++) {
        float t = sbias[o];
#pragma unroll
        for (int i = 0; i < 16; i++) t += xv[i] * sroot[i * 32 + o];
        g_x1[nid * 32 + o] = t;
    }
}

// ---------------- K3: NNConv1 message + scatter (FFMA2) ----------------------
__global__ __launch_bounds__(256) void k3_conv1(const int* __restrict__ ei,
                                                const float* __restrict__ b2) {
    __shared__ __align__(16) float swT[8192];     // 2*16*32*8
    __shared__ __align__(16) float h_sh[16 * 68];
    __shared__ __align__(16) float x_sh[64 * 16];
    __shared__ int dst_sh[64];
    int tid = threadIdx.x;
    int e0 = blockIdx.x * 64;
    for (int i = tid; i < 8192; i += 256) swT[i] = g_wT1[i];
    if (tid < 64) {
        int ge = e0 + tid;
        dst_sh[tid] = (ge < NE) ? ei[NE + ge] : 0;
    }
    for (int i = tid; i < 1024; i += 256) {
        int el = i >> 4, j = i & 15;
        int ge = e0 + el;
        h_sh[j * 68 + el] = (ge < NE) ? g_h1[ge * 16 + j] : 0.f;
    }
    for (int i = tid; i < 1024; i += 256) {
        int el = i >> 4, ii = i & 15;
        int ge = e0 + el;
        x_sh[el * 16 + ii] = (ge < NE) ? g_xbn[ei[ge] * 16 + ii] : 0.f;
    }
    __syncthreads();

    int o = tid & 31;
    int w = tid >> 5;
    float acc[8];
#pragma unroll
    for (int eL = 0; eL < 8; eL++) acc[eL] = 0.f;

#pragma unroll
    for (int ic = 0; ic < 2; ic++) {
        ull t2[4][8];
#pragma unroll
        for (int il = 0; il < 8; il++) {
            ull bp = bcast2(b2[(ic * 8 + il) * 32 + o]);
#pragma unroll
            for (int p = 0; p < 4; p++) t2[p][il] = bp;
        }

#pragma unroll 4
        for (int j = 0; j < 16; j++) {
            const ull* hp = (const ull*)&h_sh[j * 68 + w * 8];
            ulonglong2 hA = *(const ulonglong2*)hp;
            ulonglong2 hB = *(const ulonglong2*)(hp + 2);
            ull hv2[4] = {hA.x, hA.y, hB.x, hB.y};
            const float* wp = &swT[((ic * 16 + j) * 32 + o) * 8];
            float4 wa = *(const float4*)wp;
            float4 wb = *(const float4*)(wp + 4);
            ull w2[8] = {bcast2(wa.x), bcast2(wa.y), bcast2(wa.z), bcast2(wa.w),
                         bcast2(wb.x), bcast2(wb.y), bcast2(wb.z), bcast2(wb.w)};
#pragma unroll
            for (int p = 0; p < 4; p++)
#pragma unroll
                for (int il = 0; il < 8; il++) t2[p][il] = fma2(hv2[p], w2[il], t2[p][il]);
        }
#pragma unroll
        for (int p = 0; p < 4; p++)
#pragma unroll
            for (int il = 0; il < 8; il++) {
                float2 v = unpk2(t2[p][il]);
                acc[2 * p]     += x_sh[(w * 8 + 2 * p) * 16 + ic * 8 + il] * lrelu(v.x);
                acc[2 * p + 1] += x_sh[(w * 8 + 2 * p + 1) * 16 + ic * 8 + il] * lrelu(v.y);
            }
    }
#pragma unroll
    for (int eL = 0; eL < 8; eL++) {
        int ge = e0 + w * 8 + eL;
        if (ge < NE) atomicAdd(&g_x1[dst_sh[w * 8 + eL] * 32 + o], acc[eL]);
    }
}

// ---------------- K4: x2 = x1 @ l2_root + l2_bias ----------------------------
__global__ void k4_node(const float* __restrict__ root, const float* __restrict__ bias) {
    __shared__ float sroot[2048], sbias[64];
    int tid = threadIdx.x;
    for (int i = tid; i < 2048; i += 256) sroot[i] = root[i];
    if (tid < 64) sbias[tid] = bias[tid];
    __syncthreads();
    int idx = blockIdx.x * 256 + tid;
    if (idx >= NN * 64) return;
    int n = idx >> 6, o = idx & 63;
    float t = sbias[o];
#pragma unroll
    for (int i = 0; i < 32; i++) t += g_x1[n * 32 + i] * sroot[i * 64 + o];
    g_x2[idx] = t;
}

// ---------------- K5: NNConv2 (dominant): 64 edges/block, 2 batches/chunk ----
// 256 thr: o = tid&63, g = tid>>6 (4 groups). Each weight chunk (32KB, ic-slice)
// is loaded once and used for TWO 32-edge batches -> weight traffic halved vs
// 32-edge blocks. Same proven single-buffered load (inter-block overlap hides it).
__global__ __launch_bounds__(256) void k5_conv2(const int* __restrict__ ei,
                                                const float* __restrict__ b2) {
    __shared__ __align__(16) float w_sh[8192];   // 32KB chunk: [j32][o64][il4]
    __shared__ __align__(16) float h_sh[32 * 64]; // [j][e64]
    __shared__ __align__(16) float x_sh[64 * 32]; // [e][i]
    __shared__ int dst_sh[64];
    int tid = threadIdx.x;
    int e0 = blockIdx.x * 64;

    if (tid < 64) {
        int ge = e0 + tid;
        dst_sh[tid] = (ge < NE) ? ei[NE + ge] : 0;
    }
    for (int i = tid; i < 2048; i += 256) {
        int el = i >> 5, j = i & 31;
        int ge = e0 + el;
        h_sh[j * 64 + el] = (ge < NE) ? g_h2[ge * 32 + j] : 0.f;
    }
    for (int i = tid; i < 2048; i += 256) {
        int el = i >> 5, ii = i & 31;
        int ge = e0 + el;
        x_sh[el * 32 + ii] = (ge < NE) ? g_x1[ei[ge] * 32 + ii] : 0.f;
    }

    int o = tid & 63;
    int g = tid >> 6;
    float acc[2][8];
#pragma unroll
    for (int b = 0; b < 2; b++)
#pragma unroll
        for (int eL = 0; eL < 8; eL++) acc[b][eL] = 0.f;

    for (int ic = 0; ic < 8; ic++) {
        __syncthreads();   // covers initial staging (ic=0) + w_sh reuse
        for (int i = tid; i < 8192; i += 256) w_sh[i] = g_wT2[ic * 8192 + i];
        __syncthreads();

#pragma unroll
        for (int b = 0; b < 2; b++) {
            ull t2[4][4];
#pragma unroll
            for (int il = 0; il < 4; il++) {
                ull bp = bcast2(b2[(ic * 4 + il) * 64 + o]);
#pragma unroll
                for (int p = 0; p < 4; p++) t2[p][il] = bp;
            }

#pragma unroll 4
            for (int j = 0; j < 32; j++) {
                const ull* hp = (const ull*)&h_sh[j * 64 + b * 32 + g * 8];
                ulonglong2 hA = *(const ulonglong2*)hp;
                ulonglong2 hB = *(const ulonglong2*)(hp + 2);
                ull hv2[4] = {hA.x, hA.y, hB.x, hB.y};
                float4 wv = *(const float4*)&w_sh[(j * 64 + o) * 4];
                ull w2[4] = {bcast2(wv.x), bcast2(wv.y), bcast2(wv.z), bcast2(wv.w)};
#pragma unroll
                for (int p = 0; p < 4; p++)
#pragma unroll
                    for (int il = 0; il < 4; il++) t2[p][il] = fma2(hv2[p], w2[il], t2[p][il]);
            }
#pragma unroll
            for (int p = 0; p < 4; p++)
#pragma unroll
                for (int il = 0; il < 4; il++) {
                    float2 v = unpk2(t2[p][il]);
                    int eb = b * 32 + g * 8;
                    acc[b][2 * p]     += x_sh[(eb + 2 * p) * 32 + ic * 4 + il] * lrelu(v.x);
                    acc[b][2 * p + 1] += x_sh[(eb + 2 * p + 1) * 32 + ic * 4 + il] * lrelu(v.y);
                }
        }
    }
#pragma unroll
    for (int b = 0; b < 2; b++)
#pragma unroll
        for (int eL = 0; eL < 8; eL++) {
            int el = b * 32 + g * 8 + eL;
            int ge = e0 + el;
            if (ge < NE) atomicAdd(&g_x2[dst_sh[el] * 64 + o], acc[b][eL]);
        }
}

// ---------------- K6a: edge MLP layer1 (138 -> 64, FFMA2) --------------------
__global__ __launch_bounds__(256) void k6a_mlp1(const int* __restrict__ ei,
                                                const float* __restrict__ w1,
                                                const float* __restrict__ b1) {
    __shared__ float sw1[138 * 64];               // 34.5KB
    __shared__ float sb1[64];
    __shared__ __align__(16) float in_sh[138 * 20]; // [k][e] pad 20
    int tid = threadIdx.x;
    int e0 = blockIdx.x * 16;

    for (int i = tid; i < 8832; i += 256) sw1[i] = w1[i];
    if (tid < 64) sb1[tid] = b1[tid];
    for (int i = tid; i < 138 * 16; i += 256) {
        int e = i & 15, k = i >> 4;
        float v;
        if (k < 64)       v = g_x2[ei[e0 + e] * 64 + k];
        else if (k < 128) v = g_x2[ei[NE + e0 + e] * 64 + (k - 64)];
        else              v = g_ebn[(e0 + e) * 10 + (k - 128)];
        in_sh[k * 20 + e] = v;
    }
    __syncthreads();

    int o = tid & 63, g = tid >> 6;
    ull a0 = bcast2(sb1[o]);
    ull a1 = a0;
#pragma unroll 2
    for (int k = 0; k < 138; k++) {
        ull wb = bcast2(sw1[k * 64 + o]);
        ulonglong2 h = *(const ulonglong2*)&in_sh[k * 20 + g * 4];
        a0 = fma2(h.x, wb, a0);
        a1 = fma2(h.y, wb, a1);
    }
    float2 v0 = unpk2(a0), v1 = unpk2(a1);
    g_m1[(e0 + g * 4 + 0) * 64 + o] = lrelu(v0.x);
    g_m1[(e0 + g * 4 + 1) * 64 + o] = lrelu(v0.y);
    g_m1[(e0 + g * 4 + 2) * 64 + o] = lrelu(v1.x);
    g_m1[(e0 + g * 4 + 3) * 64 + o] = lrelu(v1.y);
}

// ---------------- K6b: edge MLP layers 2-5 -----------------------------------
__global__ __launch_bounds__(256) void k6b_mlp(
    const float* __restrict__ w2, const float* __restrict__ b2,
    const float* __restrict__ w3, const float* __restrict__ b3,
    const float* __restrict__ w4, const float* __restrict__ b4,
    const float* __restrict__ w5, const float* __restrict__ b5,
    float* __restrict__ out) {
    __shared__ float sw2[2048], sw3[512], sw4[128], sw5[16];
    __shared__ float sb2[32], sb3[16], sb4[8], sb5[2];
    __shared__ __align__(16) float h1_sh[64 * 36];
    __shared__ __align__(16) float h2_sh[32 * 36];
    int tid = threadIdx.x;
    int e0 = blockIdx.x * 32;

    for (int i = tid; i < 2048; i += 256) sw2[i] = w2[i];
    for (int i = tid; i < 512; i += 256) sw3[i] = w3[i];
    if (tid < 128) sw4[tid] = w4[tid];
    if (tid < 16) sw5[tid] = w5[tid];
    if (tid < 32) sb2[tid] = b2[tid];
    if (tid < 16) sb3[tid] = b3[tid];
    if (tid < 8) sb4[tid] = b4[tid];
    if (tid < 2) sb5[tid] = b5[tid];
    for (int i = tid; i < 2048; i += 256) {
        int e = i & 31, k = i >> 5;
        h1_sh[k * 36 + e] = g_m1[(e0 + e) * 64 + k];
    }
    __syncthreads();

    // layer 2: 64 -> 32 (FFMA2)
    {
        int o = tid & 31, g = tid >> 5;
        ull a0 = bcast2(sb2[o]);
        ull a1 = a0;
#pragma unroll 4
        for (int k = 0; k < 64; k++) {
            ull wb = bcast2(sw2[k * 32 + o]);
            ulonglong2 h = *(const ulonglong2*)&h1_sh[k * 36 + g * 4];
            a0 = fma2(h.x, wb, a0);
            a1 = fma2(h.y, wb, a1);
        }
        float2 v0 = unpk2(a0), v1 = unpk2(a1);
        h2_sh[o * 36 + g * 4 + 0] = lrelu(v0.x);
        h2_sh[o * 36 + g * 4 + 1] = lrelu(v0.y);
        h2_sh[o * 36 + g * 4 + 2] = lrelu(v1.x);
        h2_sh[o * 36 + g * 4 + 3] = lrelu(v1.y);
    }
    __syncthreads();

    // layers 3-5: one thread per edge
    if (tid < 32) {
        int e = tid, ge = e0 + e;
        float h2r[32];
#pragma unroll
        for (int k = 0; k < 32; k++) h2r[k] = h2_sh[k * 36 + e];
        float h3[16];
#pragma unroll
        for (int o = 0; o < 16; o++) {
            float a = sb3[o];
#pragma unroll
            for (int k = 0; k < 32; k++) a += h2r[k] * sw3[k * 16 + o];
            h3[o] = lrelu(a);
        }
        float h4[8];
#pragma unroll
        for (int o = 0; o < 8; o++) {
            float a = sb4[o];
#pragma unroll
            for (int k = 0; k < 16; k++) a += h3[k] * sw4[k * 8 + o];
            h4[o] = lrelu(a);
        }
#pragma unroll
        for (int o = 0; o < 2; o++) {
            float a = sb5[o];
#pragma unroll
            for (int k = 0; k < 8; k++) a += h4[k] * sw5[k * 2 + o];
            out[(size_t)ge * 2 + o] = a;
        }
    }
}

// ---------------- launch -----------------------------------------------------
extern "C" void kernel_launch(void* const* d_in, const int* in_sizes, int n_in,
                              void* d_out, int out_size) {
    const float* x = (const float*)d_in[0];
    const float* e = (const float*)d_in[1];
    const int* ei = (const int*)d_in[2];     // edge_index: int32
    // d_in[3] xbatch unused
    const float* bn_node_g = (const float*)d_in[4];
    const float* bn_node_b = (const float*)d_in[5];
    const float* bn_edge_g = (const float*)d_in[6];
    const float* bn_edge_b = (const float*)d_in[7];
    const float* nn1_w1 = (const float*)d_in[8];
    const float* nn1_b1 = (const float*)d_in[9];
    const float* nn1_w2 = (const float*)d_in[10];
    const float* nn1_b2 = (const float*)d_in[11];
    const float* nn2_w1 = (const float*)d_in[12];
    const float* nn2_b1 = (const float*)d_in[13];
    const float* nn2_w2 = (const float*)d_in[14];
    const float* nn2_b2 = (const float*)d_in[15];
    const float* l1_root = (const float*)d_in[16];
    const float* l1_bias = (const float*)d_in[17];
    const float* l2_root = (const float*)d_in[18];
    const float* l2_bias = (const float*)d_in[19];
    const float* mlp_w1 = (const float*)d_in[20];
    const float* mlp_b1 = (const float*)d_in[21];
    const float* mlp_w2 = (const float*)d_in[22];
    const float* mlp_b2 = (const float*)d_in[23];
    const float* mlp_w3 = (const float*)d_in[24];
    const float* mlp_b3 = (const float*)d_in[25];
    const float* mlp_w4 = (const float*)d_in[26];
    const float* mlp_b4 = (const float*)d_in[27];
    const float* mlp_w5 = (const float*)d_in[28];
    const float* mlp_b5 = (const float*)d_in[29];
    float* out = (float*)d_out;

    bn_stats_all<<<26, 256>>>(e, x);
    prep_w<<<288, 256>>>(nn1_w2, nn2_w2);
    k1_edge<<<(NE + 255) / 256, 256>>>(e, bn_edge_g, bn_edge_b, nn1_w1, nn1_b1, nn2_w1, nn2_b1);
    k2_node<<<(NN + 255) / 256, 256>>>(x, bn_node_g, bn_node_b, l1_root, l1_bias);
    k3_conv1<<<(NE + 63) / 64, 256>>>(ei, nn1_b2);
    k4_node<<<(NN * 64 + 255) / 256, 256>>>(l2_root, l2_bias);
    k5_conv2<<<(NE + 63) / 64, 256>>>(ei, nn2_b2);
    k6a_mlp1<<<NE / 16, 256>>>(ei, mlp_w1, mlp_b1);
    k6b_mlp<<<NE / 32, 256>>>(mlp_w2, mlp_b2, mlp_w3, mlp_b3,
                              mlp_w4, mlp_b4, mlp_w5, mlp_b5, out);
}

// round 9
// speedup vs baseline: 1.7725x; 1.1345x over previous
#include <cuda_runtime.h>
#include <cuda_bf16.h>
#include <cstdint>

#define NN 20000
#define NE 100000

typedef unsigned long long ull;

__device__ float g_ebn[NE * 10];
__device__ float g_h1[NE * 16];
__device__ float g_h2[NE * 32];
__device__ float g_xbn[NN * 16];
__device__ float g_x1[NN * 32];
__device__ float g_x2[NN * 64];
__device__ float g_m1[NE * 64];            // edge-MLP layer1 activations
__device__ float g_wT1[2 * 16 * 32 * 8];   // conv1 weights [ic2][j16][o32][il8]
__device__ __nv_bfloat16 g_B2h[2048 * 32]; // conv2 w2 bf16 hi, [n][k]
__device__ __nv_bfloat16 g_B2l[2048 * 32]; // conv2 w2 bf16 lo, [n][k]
__device__ float g_emean[10], g_ers[10];
__device__ float g_xmean[16], g_xrs[16];

__device__ __forceinline__ float lrelu(float v) { return v > 0.f ? v : 0.1f * v; }

// ---- packed f32x2 helpers (k3/k6) -------------------------------------------
__device__ __forceinline__ ull bcast2(float v) {
    ull r;
    unsigned u = __float_as_uint(v);
    asm("mov.b64 %0, {%1, %2};" : "=l"(r) : "r"(u), "r"(u));
    return r;
}
__device__ __forceinline__ ull fma2(ull a, ull b, ull c) {
    ull d;
    asm("fma.rn.f32x2 %0, %1, %2, %3;" : "=l"(d) : "l"(a), "l"(b), "l"(c));
    return d;
}
__device__ __forceinline__ float2 unpk2(ull v) {
    unsigned lo, hi;
    asm("mov.b64 {%0, %1}, %2;" : "=r"(lo), "=r"(hi) : "l"(v));
    return make_float2(__uint_as_float(lo), __uint_as_float(hi));
}

// ---- warp-level bf16 MMA (sm_80+ path; HMMA on sm_103) ----------------------
__device__ __forceinline__ void mma_bf16(float& c0, float& c1, float& c2, float& c3,
                                         uint32_t a0, uint32_t a1, uint32_t a2, uint32_t a3,
                                         uint32_t b0, uint32_t b1) {
    asm("mma.sync.aligned.m16n8k16.row.col.f32.bf16.bf16.f32 "
        "{%0,%1,%2,%3}, {%4,%5,%6,%7}, {%8,%9}, {%0,%1,%2,%3};"
        : "+f"(c0), "+f"(c1), "+f"(c2), "+f"(c3)
        : "r"(a0), "r"(a1), "r"(a2), "r"(a3), "r"(b0), "r"(b1));
}

// ---------------- BatchNorm statistics ---------------------------------------
__device__ void bn_stats_impl(const float* __restrict__ v, int rows, int cols, int c,
                              float* mean_out, float* rs_out) {
    int tid = threadIdx.x;
    double s = 0.0, ss = 0.0;
    for (int r = tid; r < rows; r += blockDim.x) {
        float f = v[(size_t)r * cols + c];
        s += (double)f;
        ss += (double)f * (double)f;
    }
    __shared__ double sh[256];
    sh[tid] = s; __syncthreads();
    for (int off = 128; off > 0; off >>= 1) { if (tid < off) sh[tid] += sh[tid + off]; __syncthreads(); }
    double stot = sh[0]; __syncthreads();
    sh[tid] = ss; __syncthreads();
    for (int off = 128; off > 0; off >>= 1) { if (tid < off) sh[tid] += sh[tid + off]; __syncthreads(); }
    if (tid == 0) {
        double m = stot / rows;
        double var = sh[0] / rows - m * m;
        mean_out[c] = (float)m;
        rs_out[c] = (float)(1.0 / sqrt(var + 1e-5));
    }
}

__global__ void bn_stats_all(const float* __restrict__ e, const float* __restrict__ x) {
    if (blockIdx.x < 10) bn_stats_impl(e, NE, 10, blockIdx.x, g_emean, g_ers);
    else                 bn_stats_impl(x, NN, 16, blockIdx.x - 10, g_xmean, g_xrs);
}

// ---------------- weight prep ------------------------------------------------
__global__ void prep_w(const float* __restrict__ w1g, const float* __restrict__ w2g) {
    int b = blockIdx.x;
    if (b < 32) {  // nn1_w2 [16,512] -> [ic2][j16][o32][il8]
        int idx = b * 256 + threadIdx.x;
        int il = idx & 7, o = (idx >> 3) & 31, j = (idx >> 8) & 15, ic = (idx >> 12) & 1;
        g_wT1[((ic * 16 + j) * 32 + o) * 8 + il] = w1g[j * 512 + (ic * 8 + il) * 32 + o];
    } else {       // conv2: [k32][n2048] -> bf16 hi/lo [n][k]
        int idx = (b - 32) * 256 + threadIdx.x;  // 65536
        int k = idx & 31, n = idx >> 5;
        float f = w2g[k * 2048 + n];
        __nv_bfloat16 bh = __float2bfloat16(f);
        __nv_bfloat16 bl = __float2bfloat16(f - __bfloat162float(bh));
        g_B2h[n * 32 + k] = bh;
        g_B2l[n * 32 + k] = bl;
    }
}

// ---------------- K1: edge BN + h1 + h2 --------------------------------------
__global__ void k1_edge(const float* __restrict__ e,
                        const float* __restrict__ eg, const float* __restrict__ eb,
                        const float* __restrict__ w1, const float* __restrict__ b1,
                        const float* __restrict__ w2, const float* __restrict__ b2) {
    __shared__ float sw1[160], sw2[320], sb1[16], sb2[32], sg[10], sb[10], sm[10], srs[10];
    int tid = threadIdx.x;
    for (int i = tid; i < 160; i += 256) sw1[i] = w1[i];
    for (int i = tid; i < 320; i += 256) sw2[i] = w2[i];
    if (tid < 16) sb1[tid] = b1[tid];
    if (tid < 32) sb2[tid] = b2[tid];
    if (tid < 10) { sg[tid] = eg[tid]; sb[tid] = eb[tid]; sm[tid] = g_emean[tid]; srs[tid] = g_ers[tid]; }
    __syncthreads();
    int eid = blockIdx.x * 256 + tid;
    if (eid >= NE) return;
    float ev[10];
#pragma unroll
    for (int c = 0; c < 10; c++) {
        float f = (e[eid * 10 + c] - sm[c]) * srs[c] * sg[c] + sb[c];
        ev[c] = f;
        g_ebn[eid * 10 + c] = f;
    }
#pragma unroll
    for (int o = 0; o < 16; o++) {
        float t = sb1[o];
#pragma unroll
        for (int c = 0; c < 10; c++) t += ev[c] * sw1[c * 16 + o];
        g_h1[eid * 16 + o] = lrelu(t);
    }
#pragma unroll
    for (int o = 0; o < 32; o++) {
        float t = sb2[o];
#pragma unroll
        for (int c = 0; c < 10; c++) t += ev[c] * sw2[c * 32 + o];
        g_h2[eid * 32 + o] = lrelu(t);
    }
}

// ---------------- K2: node BN + x1 = xbn @ l1_root + l1_bias -----------------
__global__ void k2_node(const float* __restrict__ x,
                        const float* __restrict__ ng, const float* __restrict__ nb,
                        const float* __restrict__ root, const float* __restrict__ bias) {
    __shared__ float sroot[512], sbias[32], sg[16], sb[16], sm[16], srs[16];
    int tid = threadIdx.x;
    for (int i = tid; i < 512; i += 256) sroot[i] = root[i];
    if (tid < 32) sbias[tid] = bias[tid];
    if (tid < 16) { sg[tid] = ng[tid]; sb[tid] = nb[tid]; sm[tid] = g_xmean[tid]; srs[tid] = g_xrs[tid]; }
    __syncthreads();
    int nid = blockIdx.x * 256 + tid;
    if (nid >= NN) return;
    float xv[16];
#pragma unroll
    for (int i = 0; i < 16; i++) {
        float f = (x[nid * 16 + i] - sm[i]) * srs[i] * sg[i] + sb[i];
        xv[i] = f;
        g_xbn[nid * 16 + i] = f;
    }
#pragma unroll
    for (int o = 0; o < 32; o++) {
        float t = sbias[o];
#pragma unroll
        for (int i = 0; i < 16; i++) t += xv[i] * sroot[i * 32 + o];
        g_x1[nid * 32 + o] = t;
    }
}

// ---------------- K3: NNConv1 message + scatter (FFMA2) ----------------------
__global__ __launch_bounds__(256) void k3_conv1(const int* __restrict__ ei,
                                                const float* __restrict__ b2) {
    __shared__ __align__(16) float swT[8192];
    __shared__ __align__(16) float h_sh[16 * 68];
    __shared__ __align__(16) float x_sh[64 * 16];
    __shared__ int dst_sh[64];
    int tid = threadIdx.x;
    int e0 = blockIdx.x * 64;
    for (int i = tid; i < 8192; i += 256) swT[i] = g_wT1[i];
    if (tid < 64) {
        int ge = e0 + tid;
        dst_sh[tid] = (ge < NE) ? ei[NE + ge] : 0;
    }
    for (int i = tid; i < 1024; i += 256) {
        int el = i >> 4, j = i & 15;
        int ge = e0 + el;
        h_sh[j * 68 + el] = (ge < NE) ? g_h1[ge * 16 + j] : 0.f;
    }
    for (int i = tid; i < 1024; i += 256) {
        int el = i >> 4, ii = i & 15;
        int ge = e0 + el;
        x_sh[el * 16 + ii] = (ge < NE) ? g_xbn[ei[ge] * 16 + ii] : 0.f;
    }
    __syncthreads();

    int o = tid & 31;
    int w = tid >> 5;
    float acc[8];
#pragma unroll
    for (int eL = 0; eL < 8; eL++) acc[eL] = 0.f;

#pragma unroll
    for (int ic = 0; ic < 2; ic++) {
        ull t2[4][8];
#pragma unroll
        for (int il = 0; il < 8; il++) {
            ull bp = bcast2(b2[(ic * 8 + il) * 32 + o]);
#pragma unroll
            for (int p = 0; p < 4; p++) t2[p][il] = bp;
        }
#pragma unroll 4
        for (int j = 0; j < 16; j++) {
            const ull* hp = (const ull*)&h_sh[j * 68 + w * 8];
            ulonglong2 hA = *(const ulonglong2*)hp;
            ulonglong2 hB = *(const ulonglong2*)(hp + 2);
            ull hv2[4] = {hA.x, hA.y, hB.x, hB.y};
            const float* wp = &swT[((ic * 16 + j) * 32 + o) * 8];
            float4 wa = *(const float4*)wp;
            float4 wb = *(const float4*)(wp + 4);
            ull w2v[8] = {bcast2(wa.x), bcast2(wa.y), bcast2(wa.z), bcast2(wa.w),
                          bcast2(wb.x), bcast2(wb.y), bcast2(wb.z), bcast2(wb.w)};
#pragma unroll
            for (int p = 0; p < 4; p++)
#pragma unroll
                for (int il = 0; il < 8; il++) t2[p][il] = fma2(hv2[p], w2v[il], t2[p][il]);
        }
#pragma unroll
        for (int p = 0; p < 4; p++)
#pragma unroll
            for (int il = 0; il < 8; il++) {
                float2 v = unpk2(t2[p][il]);
                acc[2 * p]     += x_sh[(w * 8 + 2 * p) * 16 + ic * 8 + il] * lrelu(v.x);
                acc[2 * p + 1] += x_sh[(w * 8 + 2 * p + 1) * 16 + ic * 8 + il] * lrelu(v.y);
            }
    }
#pragma unroll
    for (int eL = 0; eL < 8; eL++) {
        int ge = e0 + w * 8 + eL;
        if (ge < NE) atomicAdd(&g_x1[dst_sh[w * 8 + eL] * 32 + o], acc[eL]);
    }
}

// ---------------- K4: x2 = x1 @ l2_root + l2_bias ----------------------------
__global__ void k4_node(const float* __restrict__ root, const float* __restrict__ bias) {
    __shared__ float sroot[2048], sbias[64];
    int tid = threadIdx.x;
    for (int i = tid; i < 2048; i += 256) sroot[i] = root[i];
    if (tid < 64) sbias[tid] = bias[tid];
    __syncthreads();
    int idx = blockIdx.x * 256 + tid;
    if (idx >= NN * 64) return;
    int n = idx >> 6, o = idx & 63;
    float t = sbias[o];
#pragma unroll
    for (int i = 0; i < 32; i++) t += g_x1[n * 32 + i] * sroot[i * 64 + o];
    g_x2[idx] = t;
}

// ---------------- K5: NNConv2 via warp MMA (bf16 3-split, fp32 acc) ----------
// 64 edges/block, 128 thr (4 warps x 16 edges). GEMM: h2[64,32] x w2[32,2048].
// B streamed in 16 chunks of 128 n (hi+lo). Epilogue: +bias, lrelu, dot with
// x1[src], scatter-add.
__global__ __launch_bounds__(128) void k5_conv2_mma(const int* __restrict__ ei,
                                                    const float* __restrict__ b2) {
    __shared__ __nv_bfloat16 Bh_sh[128 * 40];   // [n][k] pad 40
    __shared__ __nv_bfloat16 Bl_sh[128 * 40];
    __shared__ __nv_bfloat16 Ah_sh[64 * 40];    // [e][k] pad 40
    __shared__ __nv_bfloat16 Al_sh[64 * 40];
    __shared__ float x_sh[64 * 33];             // [e][i] pad 33
    __shared__ float bias_sh[2048];
    __shared__ int dst_sh[64];
    int tid = threadIdx.x;
    int lane = tid & 31, w = tid >> 5;
    int e0 = blockIdx.x * 64;

    // stage A (h2 tile, bf16 split)
    for (int i = tid; i < 2048; i += 128) {
        int e = i >> 5, k = i & 31;
        int ge = e0 + e;
        float f = (ge < NE) ? g_h2[ge * 32 + k] : 0.f;
        __nv_bfloat16 bh = __float2bfloat16(f);
        Ah_sh[e * 40 + k] = bh;
        Al_sh[e * 40 + k] = __float2bfloat16(f - __bfloat162float(bh));
    }
    // stage x (gathered)
    for (int i = tid; i < 2048; i += 128) {
        int e = i >> 5, ii = i & 31;
        int ge = e0 + e;
        x_sh[e * 33 + ii] = (ge < NE) ? g_x1[ei[ge] * 32 + ii] : 0.f;
    }
    if (tid < 64) {
        int ge = e0 + tid;
        dst_sh[tid] = (ge < NE) ? ei[NE + ge] : 0;
    }
    for (int i = tid; i < 2048; i += 128) bias_sh[i] = b2[i];
    __syncthreads();

    // A fragments (built once): rows eA, eA+8; k cols 2m,2m+1,2m+8,2m+9 (+16)
    int g = lane >> 2, m = lane & 3;
    int eA = w * 16 + g;
    uint32_t ah[2][4], al[2][4];
#pragma unroll
    for (int ks = 0; ks < 2; ks++) {
        int kb = ks * 16 + 2 * m;
        ah[ks][0] = *(const uint32_t*)&Ah_sh[eA * 40 + kb];
        ah[ks][1] = *(const uint32_t*)&Ah_sh[(eA + 8) * 40 + kb];
        ah[ks][2] = *(const uint32_t*)&Ah_sh[eA * 40 + kb + 8];
        ah[ks][3] = *(const uint32_t*)&Ah_sh[(eA + 8) * 40 + kb + 8];
        al[ks][0] = *(const uint32_t*)&Al_sh[eA * 40 + kb];
        al[ks][1] = *(const uint32_t*)&Al_sh[(eA + 8) * 40 + kb];
        al[ks][2] = *(const uint32_t*)&Al_sh[eA * 40 + kb + 8];
        al[ks][3] = *(const uint32_t*)&Al_sh[(eA + 8) * 40 + kb + 8];
    }

    float acc[32];
#pragma unroll
    for (int i = 0; i < 32; i++) acc[i] = 0.f;

    for (int c = 0; c < 16; c++) {
        __syncthreads();   // protect B reuse (and initial staging)
        // load B chunk: 128 rows x 64B (hi and lo), uint4
        {
            const uint4* srcH = (const uint4*)(g_B2h + (size_t)c * 128 * 32);
            const uint4* srcL = (const uint4*)(g_B2l + (size_t)c * 128 * 32);
            for (int i = tid; i < 512; i += 128) {
                int n = i >> 2, q = i & 3;
                *((uint4*)((char*)Bh_sh + n * 80) + q) = srcH[n * 4 + q];
                *((uint4*)((char*)Bl_sh + n * 80) + q) = srcL[n * 4 + q];
            }
        }
        __syncthreads();

#pragma unroll 2
        for (int ob = 0; ob < 16; ob++) {
            const __nv_bfloat16* bhp = &Bh_sh[(ob * 8 + g) * 40];
            const __nv_bfloat16* blp = &Bl_sh[(ob * 8 + g) * 40];
            uint32_t bh00 = *(const uint32_t*)&bhp[2 * m];
            uint32_t bh01 = *(const uint32_t*)&bhp[2 * m + 8];
            uint32_t bh10 = *(const uint32_t*)&bhp[2 * m + 16];
            uint32_t bh11 = *(const uint32_t*)&bhp[2 * m + 24];
            uint32_t bl00 = *(const uint32_t*)&blp[2 * m];
            uint32_t bl01 = *(const uint32_t*)&blp[2 * m + 8];
            uint32_t bl10 = *(const uint32_t*)&blp[2 * m + 16];
            uint32_t bl11 = *(const uint32_t*)&blp[2 * m + 24];

            float cA0 = 0.f, cA1 = 0.f, cA2 = 0.f, cA3 = 0.f;
            float cB0 = 0.f, cB1 = 0.f, cB2 = 0.f, cB3 = 0.f;
            // kstep 0 chain
            mma_bf16(cA0, cA1, cA2, cA3, ah[0][0], ah[0][1], ah[0][2], ah[0][3], bh00, bh01);
            mma_bf16(cA0, cA1, cA2, cA3, al[0][0], al[0][1], al[0][2], al[0][3], bh00, bh01);
            mma_bf16(cA0, cA1, cA2, cA3, ah[0][0], ah[0][1], ah[0][2], ah[0][3], bl00, bl01);
            // kstep 1 chain (independent accumulators)
            mma_bf16(cB0, cB1, cB2, cB3, ah[1][0], ah[1][1], ah[1][2], ah[1][3], bh10, bh11);
            mma_bf16(cB0, cB1, cB2, cB3, al[1][0], al[1][1], al[1][2], al[1][3], bh10, bh11);
            mma_bf16(cB0, cB1, cB2, cB3, ah[1][0], ah[1][1], ah[1][2], ah[1][3], bl10, bl11);

            int iL = 2 * c + (ob >> 3);
            float xa = x_sh[eA * 33 + iL];
            float xb = x_sh[(eA + 8) * 33 + iL];
            int nb = c * 128 + ob * 8 + 2 * m;
            float bv0 = bias_sh[nb], bv1 = bias_sh[nb + 1];
            int ai = (ob & 7) * 2;
            acc[ai]          = fmaf(xa, lrelu(cA0 + cB0 + bv0), acc[ai]);
            acc[ai + 1]      = fmaf(xa, lrelu(cA1 + cB1 + bv1), acc[ai + 1]);
            acc[16 + ai]     = fmaf(xb, lrelu(cA2 + cB2 + bv0), acc[16 + ai]);
            acc[16 + ai + 1] = fmaf(xb, lrelu(cA3 + cB3 + bv1), acc[16 + ai + 1]);
        }
    }

    // scatter: rows eA, eA+8; o = ob*8 + 2m + {0,1}
    int o0 = 2 * m;
    if (e0 + eA < NE) {
        int d = dst_sh[eA];
#pragma unroll
        for (int ob = 0; ob < 8; ob++) {
            atomicAdd(&g_x2[d * 64 + ob * 8 + o0], acc[ob * 2]);
            atomicAdd(&g_x2[d * 64 + ob * 8 + o0 + 1], acc[ob * 2 + 1]);
        }
    }
    if (e0 + eA + 8 < NE) {
        int d = dst_sh[eA + 8];
#pragma unroll
        for (int ob = 0; ob < 8; ob++) {
            atomicAdd(&g_x2[d * 64 + ob * 8 + o0], acc[16 + ob * 2]);
            atomicAdd(&g_x2[d * 64 + ob * 8 + o0 + 1], acc[16 + ob * 2 + 1]);
        }
    }
}

// ---------------- K6a: edge MLP layer1 (138 -> 64, FFMA2) --------------------
__global__ __launch_bounds__(256) void k6a_mlp1(const int* __restrict__ ei,
                                                const float* __restrict__ w1,
                                                const float* __restrict__ b1) {
    __shared__ float sw1[138 * 64];
    __shared__ float sb1[64];
    __shared__ __align__(16) float in_sh[138 * 20];
    int tid = threadIdx.x;
    int e0 = blockIdx.x * 16;

    for (int i = tid; i < 8832; i += 256) sw1[i] = w1[i];
    if (tid < 64) sb1[tid] = b1[tid];
    for (int i = tid; i < 138 * 16; i += 256) {
        int e = i & 15, k = i >> 4;
        float v;
        if (k < 64)       v = g_x2[ei[e0 + e] * 64 + k];
        else if (k < 128) v = g_x2[ei[NE + e0 + e] * 64 + (k - 64)];
        else              v = g_ebn[(e0 + e) * 10 + (k - 128)];
        in_sh[k * 20 + e] = v;
    }
    __syncthreads();

    int o = tid & 63, g = tid >> 6;
    ull a0 = bcast2(sb1[o]);
    ull a1 = a0;
#pragma unroll 2
    for (int k = 0; k < 138; k++) {
        ull wb = bcast2(sw1[k * 64 + o]);
        ulonglong2 h = *(const ulonglong2*)&in_sh[k * 20 + g * 4];
        a0 = fma2(h.x, wb, a0);
        a1 = fma2(h.y, wb, a1);
    }
    float2 v0 = unpk2(a0), v1 = unpk2(a1);
    g_m1[(e0 + g * 4 + 0) * 64 + o] = lrelu(v0.x);
    g_m1[(e0 + g * 4 + 1) * 64 + o] = lrelu(v0.y);
    g_m1[(e0 + g * 4 + 2) * 64 + o] = lrelu(v1.x);
    g_m1[(e0 + g * 4 + 3) * 64 + o] = lrelu(v1.y);
}

// ---------------- K6b: edge MLP layers 2-5 -----------------------------------
__global__ __launch_bounds__(256) void k6b_mlp(
    const float* __restrict__ w2, const float* __restrict__ b2,
    const float* __restrict__ w3, const float* __restrict__ b3,
    const float* __restrict__ w4, const float* __restrict__ b4,
    const float* __restrict__ w5, const float* __restrict__ b5,
    float* __restrict__ out) {
    __shared__ float sw2[2048], sw3[512], sw4[128], sw5[16];
    __shared__ float sb2[32], sb3[16], sb4[8], sb5[2];
    __shared__ __align__(16) float h1_sh[64 * 36];
    __shared__ __align__(16) float h2_sh[32 * 36];
    int tid = threadIdx.x;
    int e0 = blockIdx.x * 32;

    for (int i = tid; i < 2048; i += 256) sw2[i] = w2[i];
    for (int i = tid; i < 512; i += 256) sw3[i] = w3[i];
    if (tid < 128) sw4[tid] = w4[tid];
    if (tid < 16) sw5[tid] = w5[tid];
    if (tid < 32) sb2[tid] = b2[tid];
    if (tid < 16) sb3[tid] = b3[tid];
    if (tid < 8) sb4[tid] = b4[tid];
    if (tid < 2) sb5[tid] = b5[tid];
    for (int i = tid; i < 2048; i += 256) {
        int e = i & 31, k = i >> 5;
        h1_sh[k * 36 + e] = g_m1[(e0 + e) * 64 + k];
    }
    __syncthreads();

    {
        int o = tid & 31, g = tid >> 5;
        ull a0 = bcast2(sb2[o]);
        ull a1 = a0;
#pragma unroll 4
        for (int k = 0; k < 64; k++) {
            ull wb = bcast2(sw2[k * 32 + o]);
            ulonglong2 h = *(const ulonglong2*)&h1_sh[k * 36 + g * 4];
            a0 = fma2(h.x, wb, a0);
            a1 = fma2(h.y, wb, a1);
        }
        float2 v0 = unpk2(a0), v1 = unpk2(a1);
        h2_sh[o * 36 + g * 4 + 0] = lrelu(v0.x);
        h2_sh[o * 36 + g * 4 + 1] = lrelu(v0.y);
        h2_sh[o * 36 + g * 4 + 2] = lrelu(v1.x);
        h2_sh[o * 36 + g * 4 + 3] = lrelu(v1.y);
    }
    __syncthreads();

    if (tid < 32) {
        int e = tid, ge = e0 + e;
        float h2r[32];
#pragma unroll
        for (int k = 0; k < 32; k++) h2r[k] = h2_sh[k * 36 + e];
        float h3[16];
#pragma unroll
        for (int o = 0; o < 16; o++) {
            float a = sb3[o];
#pragma unroll
            for (int k = 0; k < 32; k++) a += h2r[k] * sw3[k * 16 + o];
            h3[o] = lrelu(a);
        }
        float h4[8];
#pragma unroll
        for (int o = 0; o < 8; o++) {
            float a = sb4[o];
#pragma unroll
            for (int k = 0; k < 16; k++) a += h3[k] * sw4[k * 8 + o];
            h4[o] = lrelu(a);
        }
#pragma unroll
        for (int o = 0; o < 2; o++) {
            float a = sb5[o];
#pragma unroll
            for (int k = 0; k < 8; k++) a += h4[k] * sw5[k * 2 + o];
            out[(size_t)ge * 2 + o] = a;
        }
    }
}

// ---------------- launch -----------------------------------------------------
extern "C" void kernel_launch(void* const* d_in, const int* in_sizes, int n_in,
                              void* d_out, int out_size) {
    const float* x = (const float*)d_in[0];
    const float* e = (const float*)d_in[1];
    const int* ei = (const int*)d_in[2];     // edge_index: int32
    const float* bn_node_g = (const float*)d_in[4];
    const float* bn_node_b = (const float*)d_in[5];
    const float* bn_edge_g = (const float*)d_in[6];
    const float* bn_edge_b = (const float*)d_in[7];
    const float* nn1_w1 = (const float*)d_in[8];
    const float* nn1_b1 = (const float*)d_in[9];
    const float* nn1_w2 = (const float*)d_in[10];
    const float* nn1_b2 = (const float*)d_in[11];
    const float* nn2_w1 = (const float*)d_in[12];
    const float* nn2_b1 = (const float*)d_in[13];
    const float* nn2_w2 = (const float*)d_in[14];
    const float* nn2_b2 = (const float*)d_in[15];
    const float* l1_root = (const float*)d_in[16];
    const float* l1_bias = (const float*)d_in[17];
    const float* l2_root = (const float*)d_in[18];
    const float* l2_bias = (const float*)d_in[19];
    const float* mlp_w1 = (const float*)d_in[20];
    const float* mlp_b1 = (const float*)d_in[21];
    const float* mlp_w2 = (const float*)d_in[22];
    const float* mlp_b2 = (const float*)d_in[23];
    const float* mlp_w3 = (const float*)d_in[24];
    const float* mlp_b3 = (const float*)d_in[25];
    const float* mlp_w4 = (const float*)d_in[26];
    const float* mlp_b4 = (const float*)d_in[27];
    const float* mlp_w5 = (const float*)d_in[28];
    const float* mlp_b5 = (const float*)d_in[29];
    float* out = (float*)d_out;

    bn_stats_all<<<26, 256>>>(e, x);
    prep_w<<<288, 256>>>(nn1_w2, nn2_w2);
    k1_edge<<<(NE + 255) / 256, 256>>>(e, bn_edge_g, bn_edge_b, nn1_w1, nn1_b1, nn2_w1, nn2_b1);
    k2_node<<<(NN + 255) / 256, 256>>>(x, bn_node_g, bn_node_b, l1_root, l1_bias);
    k3_conv1<<<(NE + 63) / 64, 256>>>(ei, nn1_b2);
    k4_node<<<(NN * 64 + 255) / 256, 256>>>(l2_root, l2_bias);
    k5_conv2_mma<<<(NE + 63) / 64, 128>>>(ei, nn2_b2);
    k6a_mlp1<<<NE / 16, 256>>>(ei, mlp_w1, mlp_b1);
    k6b_mlp<<<NE / 32, 256>>>(mlp_w2, mlp_b2, mlp_w3, mlp_b3,
                              mlp_w4, mlp_b4, mlp_w5, mlp_b5, out);
}

// round 10
// speedup vs baseline: 1.8191x; 1.0263x over previous
#include <cuda_runtime.h>
#include <cuda_bf16.h>
#include <cstdint>

#define NN 20000
#define NE 100000

typedef unsigned long long ull;

__device__ float g_ebn[NE * 10];
__device__ float g_h1[NE * 16];
__device__ float g_h2[NE * 32];
__device__ float g_xbn[NN * 16];
__device__ float g_x1[NN * 32];
__device__ float g_x2[NN * 64];
__device__ float g_m1[NE * 64];            // edge-MLP layer1 activations
__device__ float g_wT1[2 * 16 * 32 * 8];   // conv1 weights [ic2][j16][o32][il8]
__device__ __nv_bfloat16 g_B2h[2048 * 32]; // conv2 w2 bf16 hi, [n][k]
__device__ __nv_bfloat16 g_B2l[2048 * 32]; // conv2 w2 bf16 lo, [n][k]
__device__ __nv_bfloat16 g_W1h[64 * 152];  // mlp_w1 bf16 hi, [n][k pad152]
__device__ __nv_bfloat16 g_W1l[64 * 152];  // mlp_w1 bf16 lo
__device__ float g_emean[10], g_ers[10];
__device__ float g_xmean[16], g_xrs[16];

__device__ __forceinline__ float lrelu(float v) { return v > 0.f ? v : 0.1f * v; }

// ---- packed f32x2 helpers (k3/k6b) ------------------------------------------
__device__ __forceinline__ ull bcast2(float v) {
    ull r;
    unsigned u = __float_as_uint(v);
    asm("mov.b64 %0, {%1, %2};" : "=l"(r) : "r"(u), "r"(u));
    return r;
}
__device__ __forceinline__ ull fma2(ull a, ull b, ull c) {
    ull d;
    asm("fma.rn.f32x2 %0, %1, %2, %3;" : "=l"(d) : "l"(a), "l"(b), "l"(c));
    return d;
}
__device__ __forceinline__ float2 unpk2(ull v) {
    unsigned lo, hi;
    asm("mov.b64 {%0, %1}, %2;" : "=r"(lo), "=r"(hi) : "l"(v));
    return make_float2(__uint_as_float(lo), __uint_as_float(hi));
}

// ---- warp-level bf16 MMA ----------------------------------------------------
__device__ __forceinline__ void mma_bf16(float& c0, float& c1, float& c2, float& c3,
                                         uint32_t a0, uint32_t a1, uint32_t a2, uint32_t a3,
                                         uint32_t b0, uint32_t b1) {
    asm("mma.sync.aligned.m16n8k16.row.col.f32.bf16.bf16.f32 "
        "{%0,%1,%2,%3}, {%4,%5,%6,%7}, {%8,%9}, {%0,%1,%2,%3};"
        : "+f"(c0), "+f"(c1), "+f"(c2), "+f"(c3)
        : "r"(a0), "r"(a1), "r"(a2), "r"(a3), "r"(b0), "r"(b1));
}

// ---------------- BatchNorm statistics ---------------------------------------
__device__ void bn_stats_impl(const float* __restrict__ v, int rows, int cols, int c,
                              float* mean_out, float* rs_out) {
    int tid = threadIdx.x;
    double s = 0.0, ss = 0.0;
    for (int r = tid; r < rows; r += blockDim.x) {
        float f = v[(size_t)r * cols + c];
        s += (double)f;
        ss += (double)f * (double)f;
    }
    __shared__ double sh[256];
    sh[tid] = s; __syncthreads();
    for (int off = 128; off > 0; off >>= 1) { if (tid < off) sh[tid] += sh[tid + off]; __syncthreads(); }
    double stot = sh[0]; __syncthreads();
    sh[tid] = ss; __syncthreads();
    for (int off = 128; off > 0; off >>= 1) { if (tid < off) sh[tid] += sh[tid + off]; __syncthreads(); }
    if (tid == 0) {
        double m = stot / rows;
        double var = sh[0] / rows - m * m;
        mean_out[c] = (float)m;
        rs_out[c] = (float)(1.0 / sqrt(var + 1e-5));
    }
}

__global__ void bn_stats_all(const float* __restrict__ e, const float* __restrict__ x) {
    if (blockIdx.x < 10) bn_stats_impl(e, NE, 10, blockIdx.x, g_emean, g_ers);
    else                 bn_stats_impl(x, NN, 16, blockIdx.x - 10, g_xmean, g_xrs);
}

// ---------------- weight prep ------------------------------------------------
__global__ void prep_w(const float* __restrict__ w1g, const float* __restrict__ w2g,
                       const float* __restrict__ mw1) {
    int b = blockIdx.x;
    if (b < 32) {  // nn1_w2 [16,512] -> [ic2][j16][o32][il8]
        int idx = b * 256 + threadIdx.x;
        int il = idx & 7, o = (idx >> 3) & 31, j = (idx >> 8) & 15, ic = (idx >> 12) & 1;
        g_wT1[((ic * 16 + j) * 32 + o) * 8 + il] = w1g[j * 512 + (ic * 8 + il) * 32 + o];
    } else if (b < 288) {  // conv2: [k32][n2048] -> bf16 hi/lo [n][k]
        int idx = (b - 32) * 256 + threadIdx.x;  // 65536
        int k = idx & 31, n = idx >> 5;
        float f = w2g[k * 2048 + n];
        __nv_bfloat16 bh = __float2bfloat16(f);
        __nv_bfloat16 bl = __float2bfloat16(f - __bfloat162float(bh));
        g_B2h[n * 32 + k] = bh;
        g_B2l[n * 32 + k] = bl;
    } else {  // mlp_w1 [138,64] -> bf16 hi/lo [n64][k152 pad-zero]
        int idx = (b - 288) * 256 + threadIdx.x;  // 9728
        int n = idx / 152, k = idx - n * 152;
        float f = (k < 138) ? mw1[k * 64 + n] : 0.f;
        __nv_bfloat16 bh = __float2bfloat16(f);
        g_W1h[idx] = bh;
        g_W1l[idx] = __float2bfloat16(f - __bfloat162float(bh));
    }
}

// ---------------- K1: edge BN + h1 + h2 --------------------------------------
__global__ void k1_edge(const float* __restrict__ e,
                        const float* __restrict__ eg, const float* __restrict__ eb,
                        const float* __restrict__ w1, const float* __restrict__ b1,
                        const float* __restrict__ w2, const float* __restrict__ b2) {
    __shared__ float sw1[160], sw2[320], sb1[16], sb2[32], sg[10], sb[10], sm[10], srs[10];
    int tid = threadIdx.x;
    for (int i = tid; i < 160; i += 256) sw1[i] = w1[i];
    for (int i = tid; i < 320; i += 256) sw2[i] = w2[i];
    if (tid < 16) sb1[tid] = b1[tid];
    if (tid < 32) sb2[tid] = b2[tid];
    if (tid < 10) { sg[tid] = eg[tid]; sb[tid] = eb[tid]; sm[tid] = g_emean[tid]; srs[tid] = g_ers[tid]; }
    __syncthreads();
    int eid = blockIdx.x * 256 + tid;
    if (eid >= NE) return;
    float ev[10];
#pragma unroll
    for (int c = 0; c < 10; c++) {
        float f = (e[eid * 10 + c] - sm[c]) * srs[c] * sg[c] + sb[c];
        ev[c] = f;
        g_ebn[eid * 10 + c] = f;
    }
#pragma unroll
    for (int o = 0; o < 16; o++) {
        float t = sb1[o];
#pragma unroll
        for (int c = 0; c < 10; c++) t += ev[c] * sw1[c * 16 + o];
        g_h1[eid * 16 + o] = lrelu(t);
    }
#pragma unroll
    for (int o = 0; o < 32; o++) {
        float t = sb2[o];
#pragma unroll
        for (int c = 0; c < 10; c++) t += ev[c] * sw2[c * 32 + o];
        g_h2[eid * 32 + o] = lrelu(t);
    }
}

// ---------------- K2: node BN + x1 = xbn @ l1_root + l1_bias -----------------
__global__ void k2_node(const float* __restrict__ x,
                        const float* __restrict__ ng, const float* __restrict__ nb,
                        const float* __restrict__ root, const float* __restrict__ bias) {
    __shared__ float sroot[512], sbias[32], sg[16], sb[16], sm[16], srs[16];
    int tid = threadIdx.x;
    for (int i = tid; i < 512; i += 256) sroot[i] = root[i];
    if (tid < 32) sbias[tid] = bias[tid];
    if (tid < 16) { sg[tid] = ng[tid]; sb[tid] = nb[tid]; sm[tid] = g_xmean[tid]; srs[tid] = g_xrs[tid]; }
    __syncthreads();
    int nid = blockIdx.x * 256 + tid;
    if (nid >= NN) return;
    float xv[16];
#pragma unroll
    for (int i = 0; i < 16; i++) {
        float f = (x[nid * 16 + i] - sm[i]) * srs[i] * sg[i] + sb[i];
        xv[i] = f;
        g_xbn[nid * 16 + i] = f;
    }
#pragma unroll
    for (int o = 0; o < 32; o++) {
        float t = sbias[o];
#pragma unroll
        for (int i = 0; i < 16; i++) t += xv[i] * sroot[i * 32 + o];
        g_x1[nid * 32 + o] = t;
    }
}

// ---------------- K3: NNConv1 message + scatter (FFMA2) ----------------------
__global__ __launch_bounds__(256) void k3_conv1(const int* __restrict__ ei,
                                                const float* __restrict__ b2) {
    __shared__ __align__(16) float swT[8192];
    __shared__ __align__(16) float h_sh[16 * 68];
    __shared__ __align__(16) float x_sh[64 * 16];
    __shared__ int dst_sh[64];
    int tid = threadIdx.x;
    int e0 = blockIdx.x * 64;
    for (int i = tid; i < 8192; i += 256) swT[i] = g_wT1[i];
    if (tid < 64) {
        int ge = e0 + tid;
        dst_sh[tid] = (ge < NE) ? ei[NE + ge] : 0;
    }
    for (int i = tid; i < 1024; i += 256) {
        int el = i >> 4, j = i & 15;
        int ge = e0 + el;
        h_sh[j * 68 + el] = (ge < NE) ? g_h1[ge * 16 + j] : 0.f;
    }
    for (int i = tid; i < 1024; i += 256) {
        int el = i >> 4, ii = i & 15;
        int ge = e0 + el;
        x_sh[el * 16 + ii] = (ge < NE) ? g_xbn[ei[ge] * 16 + ii] : 0.f;
    }
    __syncthreads();

    int o = tid & 31;
    int w = tid >> 5;
    float acc[8];
#pragma unroll
    for (int eL = 0; eL < 8; eL++) acc[eL] = 0.f;

#pragma unroll
    for (int ic = 0; ic < 2; ic++) {
        ull t2[4][8];
#pragma unroll
        for (int il = 0; il < 8; il++) {
            ull bp = bcast2(b2[(ic * 8 + il) * 32 + o]);
#pragma unroll
            for (int p = 0; p < 4; p++) t2[p][il] = bp;
        }
#pragma unroll 4
        for (int j = 0; j < 16; j++) {
            const ull* hp = (const ull*)&h_sh[j * 68 + w * 8];
            ulonglong2 hA = *(const ulonglong2*)hp;
            ulonglong2 hB = *(const ulonglong2*)(hp + 2);
            ull hv2[4] = {hA.x, hA.y, hB.x, hB.y};
            const float* wp = &swT[((ic * 16 + j) * 32 + o) * 8];
            float4 wa = *(const float4*)wp;
            float4 wb = *(const float4*)(wp + 4);
            ull w2v[8] = {bcast2(wa.x), bcast2(wa.y), bcast2(wa.z), bcast2(wa.w),
                          bcast2(wb.x), bcast2(wb.y), bcast2(wb.z), bcast2(wb.w)};
#pragma unroll
            for (int p = 0; p < 4; p++)
#pragma unroll
                for (int il = 0; il < 8; il++) t2[p][il] = fma2(hv2[p], w2v[il], t2[p][il]);
        }
#pragma unroll
        for (int p = 0; p < 4; p++)
#pragma unroll
            for (int il = 0; il < 8; il++) {
                float2 v = unpk2(t2[p][il]);
                acc[2 * p]     += x_sh[(w * 8 + 2 * p) * 16 + ic * 8 + il] * lrelu(v.x);
                acc[2 * p + 1] += x_sh[(w * 8 + 2 * p + 1) * 16 + ic * 8 + il] * lrelu(v.y);
            }
    }
#pragma unroll
    for (int eL = 0; eL < 8; eL++) {
        int ge = e0 + w * 8 + eL;
        if (ge < NE) atomicAdd(&g_x1[dst_sh[w * 8 + eL] * 32 + o], acc[eL]);
    }
}

// ---------------- K4: x2 = x1 @ l2_root + l2_bias ----------------------------
__global__ void k4_node(const float* __restrict__ root, const float* __restrict__ bias) {
    __shared__ float sroot[2048], sbias[64];
    int tid = threadIdx.x;
    for (int i = tid; i < 2048; i += 256) sroot[i] = root[i];
    if (tid < 64) sbias[tid] = bias[tid];
    __syncthreads();
    int idx = blockIdx.x * 256 + tid;
    if (idx >= NN * 64) return;
    int n = idx >> 6, o = idx & 63;
    float t = sbias[o];
#pragma unroll
    for (int i = 0; i < 32; i++) t += g_x1[n * 32 + i] * sroot[i * 64 + o];
    g_x2[idx] = t;
}

// ---------------- K5: NNConv2 via warp MMA (bf16 3-split, reg dbl-buffer) ----
__global__ __launch_bounds__(128) void k5_conv2_mma(const int* __restrict__ ei,
                                                    const float* __restrict__ b2) {
    __shared__ __nv_bfloat16 Bh_sh[128 * 40];   // [n][k] pad 40
    __shared__ __nv_bfloat16 Bl_sh[128 * 40];
    __shared__ __nv_bfloat16 Ah_sh[64 * 40];    // [e][k] pad 40
    __shared__ __nv_bfloat16 Al_sh[64 * 40];
    __shared__ float x_sh[64 * 33];             // [e][i] pad 33
    __shared__ float bias_sh[2048];
    __shared__ int dst_sh[64];
    int tid = threadIdx.x;
    int lane = tid & 31, w = tid >> 5;
    int e0 = blockIdx.x * 64;

    // preload B chunk 0 into registers (overlaps with staging below)
    uint4 rH[4], rL[4];
    int n_ = tid >> 2, q_ = tid & 3;
    {
        const uint4* srcH = (const uint4*)(g_B2h);
        const uint4* srcL = (const uint4*)(g_B2l);
#pragma unroll
        for (int j = 0; j < 4; j++) {
            rH[j] = srcH[(n_ + 32 * j) * 4 + q_];
            rL[j] = srcL[(n_ + 32 * j) * 4 + q_];
        }
    }

    // stage A (h2 tile, bf16 split)
    for (int i = tid; i < 2048; i += 128) {
        int e = i >> 5, k = i & 31;
        int ge = e0 + e;
        float f = (ge < NE) ? g_h2[ge * 32 + k] : 0.f;
        __nv_bfloat16 bh = __float2bfloat16(f);
        Ah_sh[e * 40 + k] = bh;
        Al_sh[e * 40 + k] = __float2bfloat16(f - __bfloat162float(bh));
    }
    // stage x (gathered)
    for (int i = tid; i < 2048; i += 128) {
        int e = i >> 5, ii = i & 31;
        int ge = e0 + e;
        x_sh[e * 33 + ii] = (ge < NE) ? g_x1[ei[ge] * 32 + ii] : 0.f;
    }
    if (tid < 64) {
        int ge = e0 + tid;
        dst_sh[tid] = (ge < NE) ? ei[NE + ge] : 0;
    }
    for (int i = tid; i < 2048; i += 128) bias_sh[i] = b2[i];
    __syncthreads();

    // A fragments (built once)
    int g = lane >> 2, m = lane & 3;
    int eA = w * 16 + g;
    uint32_t ah[2][4], al[2][4];
#pragma unroll
    for (int ks = 0; ks < 2; ks++) {
        int kb = ks * 16 + 2 * m;
        ah[ks][0] = *(const uint32_t*)&Ah_sh[eA * 40 + kb];
        ah[ks][1] = *(const uint32_t*)&Ah_sh[(eA + 8) * 40 + kb];
        ah[ks][2] = *(const uint32_t*)&Ah_sh[eA * 40 + kb + 8];
        ah[ks][3] = *(const uint32_t*)&Ah_sh[(eA + 8) * 40 + kb + 8];
        al[ks][0] = *(const uint32_t*)&Al_sh[eA * 40 + kb];
        al[ks][1] = *(const uint32_t*)&Al_sh[(eA + 8) * 40 + kb];
        al[ks][2] = *(const uint32_t*)&Al_sh[eA * 40 + kb + 8];
        al[ks][3] = *(const uint32_t*)&Al_sh[(eA + 8) * 40 + kb + 8];
    }

    float acc[32];
#pragma unroll
    for (int i = 0; i < 32; i++) acc[i] = 0.f;

    for (int c = 0; c < 16; c++) {
        // smem free (first iter: staging sync above doubles as the guard)
        if (c > 0) __syncthreads();
        // store prefetched chunk to smem
#pragma unroll
        for (int j = 0; j < 4; j++) {
            *((uint4*)((char*)Bh_sh + (n_ + 32 * j) * 80) + q_) = rH[j];
            *((uint4*)((char*)Bl_sh + (n_ + 32 * j) * 80) + q_) = rL[j];
        }
        __syncthreads();
        // prefetch next chunk (overlaps with MMA compute)
        if (c + 1 < 16) {
            const uint4* srcH = (const uint4*)(g_B2h + (size_t)(c + 1) * 4096);
            const uint4* srcL = (const uint4*)(g_B2l + (size_t)(c + 1) * 4096);
#pragma unroll
            for (int j = 0; j < 4; j++) {
                rH[j] = srcH[(n_ + 32 * j) * 4 + q_];
                rL[j] = srcL[(n_ + 32 * j) * 4 + q_];
            }
        }

#pragma unroll 2
        for (int ob = 0; ob < 16; ob++) {
            const __nv_bfloat16* bhp = &Bh_sh[(ob * 8 + g) * 40];
            const __nv_bfloat16* blp = &Bl_sh[(ob * 8 + g) * 40];
            uint32_t bh00 = *(const uint32_t*)&bhp[2 * m];
            uint32_t bh01 = *(const uint32_t*)&bhp[2 * m + 8];
            uint32_t bh10 = *(const uint32_t*)&bhp[2 * m + 16];
            uint32_t bh11 = *(const uint32_t*)&bhp[2 * m + 24];
            uint32_t bl00 = *(const uint32_t*)&blp[2 * m];
            uint32_t bl01 = *(const uint32_t*)&blp[2 * m + 8];
            uint32_t bl10 = *(const uint32_t*)&blp[2 * m + 16];
            uint32_t bl11 = *(const uint32_t*)&blp[2 * m + 24];

            float cA0 = 0.f, cA1 = 0.f, cA2 = 0.f, cA3 = 0.f;
            float cB0 = 0.f, cB1 = 0.f, cB2 = 0.f, cB3 = 0.f;
            mma_bf16(cA0, cA1, cA2, cA3, ah[0][0], ah[0][1], ah[0][2], ah[0][3], bh00, bh01);
            mma_bf16(cA0, cA1, cA2, cA3, al[0][0], al[0][1], al[0][2], al[0][3], bh00, bh01);
            mma_bf16(cA0, cA1, cA2, cA3, ah[0][0], ah[0][1], ah[0][2], ah[0][3], bl00, bl01);
            mma_bf16(cB0, cB1, cB2, cB3, ah[1][0], ah[1][1], ah[1][2], ah[1][3], bh10, bh11);
            mma_bf16(cB0, cB1, cB2, cB3, al[1][0], al[1][1], al[1][2], al[1][3], bh10, bh11);
            mma_bf16(cB0, cB1, cB2, cB3, ah[1][0], ah[1][1], ah[1][2], ah[1][3], bl10, bl11);

            int iL = 2 * c + (ob >> 3);
            float xa = x_sh[eA * 33 + iL];
            float xb = x_sh[(eA + 8) * 33 + iL];
            int nb = c * 128 + ob * 8 + 2 * m;
            float bv0 = bias_sh[nb], bv1 = bias_sh[nb + 1];
            int ai = (ob & 7) * 2;
            acc[ai]          = fmaf(xa, lrelu(cA0 + cB0 + bv0), acc[ai]);
            acc[ai + 1]      = fmaf(xa, lrelu(cA1 + cB1 + bv1), acc[ai + 1]);
            acc[16 + ai]     = fmaf(xb, lrelu(cA2 + cB2 + bv0), acc[16 + ai]);
            acc[16 + ai + 1] = fmaf(xb, lrelu(cA3 + cB3 + bv1), acc[16 + ai + 1]);
        }
    }

    int o0 = 2 * m;
    if (e0 + eA < NE) {
        int d = dst_sh[eA];
#pragma unroll
        for (int ob = 0; ob < 8; ob++) {
            atomicAdd(&g_x2[d * 64 + ob * 8 + o0], acc[ob * 2]);
            atomicAdd(&g_x2[d * 64 + ob * 8 + o0 + 1], acc[ob * 2 + 1]);
        }
    }
    if (e0 + eA + 8 < NE) {
        int d = dst_sh[eA + 8];
#pragma unroll
        for (int ob = 0; ob < 8; ob++) {
            atomicAdd(&g_x2[d * 64 + ob * 8 + o0], acc[16 + ob * 2]);
            atomicAdd(&g_x2[d * 64 + ob * 8 + o0 + 1], acc[16 + ob * 2 + 1]);
        }
    }
}

// ---------------- K6a: edge MLP layer1 via warp MMA (bf16 3-split) -----------
// 16 edges/block, 128 thr (4 warps). GEMM [16,144] x [144,64] (k padded, zeros).
__global__ __launch_bounds__(128) void k6a_mma(const int* __restrict__ ei,
                                               const float* __restrict__ b1) {
    __shared__ __nv_bfloat16 Ah[16 * 152], Al[16 * 152];  // [e][k]
    __shared__ __nv_bfloat16 Bh[64 * 152], Bl[64 * 152];  // [n][k]
    __shared__ float sb1[64];
    __shared__ int se[32];   // src[16] | dst[16]
    int tid = threadIdx.x;
    int e0 = blockIdx.x * 16;

    if (tid < 16) se[tid] = ei[e0 + tid];
    else if (tid < 32) se[tid] = ei[NE + e0 + tid - 16];
    if (tid >= 64 && tid < 128) sb1[tid - 64] = b1[tid - 64];
    // copy W1 tiles (layout matches smem exactly): 1216 uint4 each
    {
        const uint4* sH = (const uint4*)g_W1h;
        const uint4* sL = (const uint4*)g_W1l;
        uint4* dH = (uint4*)Bh;
        uint4* dL = (uint4*)Bl;
        for (int i = tid; i < 1216; i += 128) { dH[i] = sH[i]; dL[i] = sL[i]; }
    }
    __syncthreads();   // se ready

    // stage A: concat(x2[src], x2[dst], ebn) bf16 split, k 138..151 zero
    for (int i = tid; i < 16 * 152; i += 128) {
        int e = i / 152, k = i - e * 152;
        float v = 0.f;
        if (k < 64)       v = g_x2[se[e] * 64 + k];
        else if (k < 128) v = g_x2[se[16 + e] * 64 + (k - 64)];
        else if (k < 138) v = g_ebn[(e0 + e) * 10 + (k - 128)];
        __nv_bfloat16 bh = __float2bfloat16(v);
        Ah[i] = bh;
        Al[i] = __float2bfloat16(v - __bfloat162float(bh));
    }
    __syncthreads();

    int lane = tid & 31, w = tid >> 5, g = lane >> 2, m = lane & 3;
#pragma unroll
    for (int ob = 0; ob < 2; ob++) {
        int n0 = (w * 2 + ob) * 8;
        float c0 = 0.f, c1 = 0.f, c2 = 0.f, c3 = 0.f;
#pragma unroll
        for (int ks = 0; ks < 9; ks++) {
            int kb = ks * 16 + 2 * m;
            uint32_t a0 = *(const uint32_t*)&Ah[g * 152 + kb];
            uint32_t a1 = *(const uint32_t*)&Ah[(g + 8) * 152 + kb];
            uint32_t a2 = *(const uint32_t*)&Ah[g * 152 + kb + 8];
            uint32_t a3 = *(const uint32_t*)&Ah[(g + 8) * 152 + kb + 8];
            uint32_t l0 = *(const uint32_t*)&Al[g * 152 + kb];
            uint32_t l1 = *(const uint32_t*)&Al[(g + 8) * 152 + kb];
            uint32_t l2 = *(const uint32_t*)&Al[g * 152 + kb + 8];
            uint32_t l3 = *(const uint32_t*)&Al[(g + 8) * 152 + kb + 8];
            const __nv_bfloat16* bp = &Bh[(n0 + g) * 152 + ks * 16];
            const __nv_bfloat16* lp = &Bl[(n0 + g) * 152 + ks * 16];
            uint32_t b0 = *(const uint32_t*)&bp[2 * m];
            uint32_t b1r = *(const uint32_t*)&bp[2 * m + 8];
            uint32_t bl0 = *(const uint32_t*)&lp[2 * m];
            uint32_t bl1 = *(const uint32_t*)&lp[2 * m + 8];
            mma_bf16(c0, c1, c2, c3, a0, a1, a2, a3, b0, b1r);
            mma_bf16(c0, c1, c2, c3, l0, l1, l2, l3, b0, b1r);
            mma_bf16(c0, c1, c2, c3, a0, a1, a2, a3, bl0, bl1);
        }
        int col = n0 + 2 * m;
        g_m1[(e0 + g) * 64 + col]         = lrelu(c0 + sb1[col]);
        g_m1[(e0 + g) * 64 + col + 1]     = lrelu(c1 + sb1[col + 1]);
        g_m1[(e0 + g + 8) * 64 + col]     = lrelu(c2 + sb1[col]);
        g_m1[(e0 + g + 8) * 64 + col + 1] = lrelu(c3 + sb1[col + 1]);
    }
}

// ---------------- K6b: edge MLP layers 2-5 -----------------------------------
__global__ __launch_bounds__(256) void k6b_mlp(
    const float* __restrict__ w2, const float* __restrict__ b2,
    const float* __restrict__ w3, const float* __restrict__ b3,
    const float* __restrict__ w4, const float* __restrict__ b4,
    const float* __restrict__ w5, const float* __restrict__ b5,
    float* __restrict__ out) {
    __shared__ float sw2[2048], sw3[512], sw4[128], sw5[16];
    __shared__ float sb2[32], sb3[16], sb4[8], sb5[2];
    __shared__ __align__(16) float h1_sh[64 * 36];
    __shared__ __align__(16) float h2_sh[32 * 36];
    int tid = threadIdx.x;
    int e0 = blockIdx.x * 32;

    for (int i = tid; i < 2048; i += 256) sw2[i] = w2[i];
    for (int i = tid; i < 512; i += 256) sw3[i] = w3[i];
    if (tid < 128) sw4[tid] = w4[tid];
    if (tid < 16) sw5[tid] = w5[tid];
    if (tid < 32) sb2[tid] = b2[tid];
    if (tid < 16) sb3[tid] = b3[tid];
    if (tid < 8) sb4[tid] = b4[tid];
    if (tid < 2) sb5[tid] = b5[tid];
    for (int i = tid; i < 2048; i += 256) {
        int e = i & 31, k = i >> 5;
        h1_sh[k * 36 + e] = g_m1[(e0 + e) * 64 + k];
    }
    __syncthreads();

    {
        int o = tid & 31, g = tid >> 5;
        ull a0 = bcast2(sb2[o]);
        ull a1 = a0;
#pragma unroll 4
        for (int k = 0; k < 64; k++) {
            ull wb = bcast2(sw2[k * 32 + o]);
            ulonglong2 h = *(const ulonglong2*)&h1_sh[k * 36 + g * 4];
            a0 = fma2(h.x, wb, a0);
            a1 = fma2(h.y, wb, a1);
        }
        float2 v0 = unpk2(a0), v1 = unpk2(a1);
        h2_sh[o * 36 + g * 4 + 0] = lrelu(v0.x);
        h2_sh[o * 36 + g * 4 + 1] = lrelu(v0.y);
        h2_sh[o * 36 + g * 4 + 2] = lrelu(v1.x);
        h2_sh[o * 36 + g * 4 + 3] = lrelu(v1.y);
    }
    __syncthreads();

    if (tid < 32) {
        int e = tid, ge = e0 + e;
        float h2r[32];
#pragma unroll
        for (int k = 0; k < 32; k++) h2r[k] = h2_sh[k * 36 + e];
        float h3[16];
#pragma unroll
        for (int o = 0; o < 16; o++) {
            float a = sb3[o];
#pragma unroll
            for (int k = 0; k < 32; k++) a += h2r[k] * sw3[k * 16 + o];
            h3[o] = lrelu(a);
        }
        float h4[8];
#pragma unroll
        for (int o = 0; o < 8; o++) {
            float a = sb4[o];
#pragma unroll
            for (int k = 0; k < 16; k++) a += h3[k] * sw4[k * 8 + o];
            h4[o] = lrelu(a);
        }
#pragma unroll
        for (int o = 0; o < 2; o++) {
            float a = sb5[o];
#pragma unroll
            for (int k = 0; k < 8; k++) a += h4[k] * sw5[k * 2 + o];
            out[(size_t)ge * 2 + o] = a;
        }
    }
}

// ---------------- launch -----------------------------------------------------
extern "C" void kernel_launch(void* const* d_in, const int* in_sizes, int n_in,
                              void* d_out, int out_size) {
    const float* x = (const float*)d_in[0];
    const float* e = (const float*)d_in[1];
    const int* ei = (const int*)d_in[2];     // edge_index: int32
    const float* bn_node_g = (const float*)d_in[4];
    const float* bn_node_b = (const float*)d_in[5];
    const float* bn_edge_g = (const float*)d_in[6];
    const float* bn_edge_b = (const float*)d_in[7];
    const float* nn1_w1 = (const float*)d_in[8];
    const float* nn1_b1 = (const float*)d_in[9];
    const float* nn1_w2 = (const float*)d_in[10];
    const float* nn1_b2 = (const float*)d_in[11];
    const float* nn2_w1 = (const float*)d_in[12];
    const float* nn2_b1 = (const float*)d_in[13];
    const float* nn2_w2 = (const float*)d_in[14];
    const float* nn2_b2 = (const float*)d_in[15];
    const float* l1_root = (const float*)d_in[16];
    const float* l1_bias = (const float*)d_in[17];
    const float* l2_root = (const float*)d_in[18];
    const float* l2_bias = (const float*)d_in[19];
    const float* mlp_w1 = (const float*)d_in[20];
    const float* mlp_b1 = (const float*)d_in[21];
    const float* mlp_w2 = (const float*)d_in[22];
    const float* mlp_b2 = (const float*)d_in[23];
    const float* mlp_w3 = (const float*)d_in[24];
    const float* mlp_b3 = (const float*)d_in[25];
    const float* mlp_w4 = (const float*)d_in[26];
    const float* mlp_b4 = (const float*)d_in[27];
    const float* mlp_w5 = (const float*)d_in[28];
    const float* mlp_b5 = (const float*)d_in[29];
    float* out = (float*)d_out;

    bn_stats_all<<<26, 256>>>(e, x);
    prep_w<<<326, 256>>>(nn1_w2, nn2_w2, mlp_w1);
    k1_edge<<<(NE + 255) / 256, 256>>>(e, bn_edge_g, bn_edge_b, nn1_w1, nn1_b1, nn2_w1, nn2_b1);
    k2_node<<<(NN + 255) / 256, 256>>>(x, bn_node_g, bn_node_b, l1_root, l1_bias);
    k3_conv1<<<(NE + 63) / 64, 256>>>(ei, nn1_b2);
    k4_node<<<(NN * 64 + 255) / 256, 256>>>(l2_root, l2_bias);
    k5_conv2_mma<<<(NE + 63) / 64, 128>>>(ei, nn2_b2);
    k6a_mma<<<NE / 16, 128>>>(ei, mlp_b1);
    k6b_mlp<<<NE / 32, 256>>>(mlp_w2, mlp_b2, mlp_w3, mlp_b3,
                              mlp_w4, mlp_b4, mlp_w5, mlp_b5, out);
}

// round 12
// speedup vs baseline: 2.1267x; 1.1691x over previous
#include <cuda_runtime.h>
#include <cuda_bf16.h>
#include <cstdint>

#define NN 20000
#define NE 100000

typedef unsigned long long ull;

__device__ float g_ebn[NE * 10];
__device__ float g_h1[NE * 16];
__device__ float g_h2[NE * 32];
__device__ float g_xbn[NN * 16];
__device__ float g_x1[NN * 32];
__device__ float g_x2[NN * 64];
__device__ float g_m1[NE * 64];            // edge-MLP layer1 activations
__device__ __nv_bfloat16 g_C1h[512 * 16];  // conv1 w2 bf16 hi, [n][k]
__device__ __nv_bfloat16 g_C1l[512 * 16];  // conv1 w2 bf16 lo
__device__ __nv_bfloat16 g_B2h[2048 * 32]; // conv2 w2 bf16 hi, [n][k]
__device__ __nv_bfloat16 g_B2l[2048 * 32]; // conv2 w2 bf16 lo
__device__ __nv_bfloat16 g_W1h[64 * 152];  // mlp_w1 bf16 hi, [n][k pad152]
__device__ __nv_bfloat16 g_W1l[64 * 152];  // mlp_w1 bf16 lo
__device__ double g_dsum[26], g_dss[26];
__device__ float g_emean[10], g_ers[10];
__device__ float g_xmean[16], g_xrs[16];

__device__ __forceinline__ float lrelu(float v) { return v > 0.f ? v : 0.1f * v; }

// ---- packed f32x2 helpers (k6b) ---------------------------------------------
__device__ __forceinline__ ull bcast2(float v) {
    ull r;
    unsigned u = __float_as_uint(v);
    asm("mov.b64 %0, {%1, %2};" : "=l"(r) : "r"(u), "r"(u));
    return r;
}
__device__ __forceinline__ ull fma2(ull a, ull b, ull c) {
    ull d;
    asm("fma.rn.f32x2 %0, %1, %2, %3;" : "=l"(d) : "l"(a), "l"(b), "l"(c));
    return d;
}
__device__ __forceinline__ float2 unpk2(ull v) {
    unsigned lo, hi;
    asm("mov.b64 {%0, %1}, %2;" : "=r"(lo), "=r"(hi) : "l"(v));
    return make_float2(__uint_as_float(lo), __uint_as_float(hi));
}

// ---- warp-level bf16 MMA ----------------------------------------------------
__device__ __forceinline__ void mma_bf16(float& c0, float& c1, float& c2, float& c3,
                                         uint32_t a0, uint32_t a1, uint32_t a2, uint32_t a3,
                                         uint32_t b0, uint32_t b1) {
    asm("mma.sync.aligned.m16n8k16.row.col.f32.bf16.bf16.f32 "
        "{%0,%1,%2,%3}, {%4,%5,%6,%7}, {%8,%9}, {%0,%1,%2,%3};"
        : "+f"(c0), "+f"(c1), "+f"(c2), "+f"(c3)
        : "r"(a0), "r"(a1), "r"(a2), "r"(a3), "r"(b0), "r"(b1));
}

// ---------------- BatchNorm statistics (coalesced, fixed-col-per-thread) -----
__global__ void bn_init() {
    int t = threadIdx.x;
    if (t < 26) { g_dsum[t] = 0.0; g_dss[t] = 0.0; }
}

// 320 threads: 320 % 10 == 0 and 320 % 16 == 0 -> column fixed per thread.
__global__ void bn_acc(const float* __restrict__ e, const float* __restrict__ x) {
    __shared__ double s_sh[320], ss_sh[320];
    int b = blockIdx.x, t = threadIdx.x;
    double s = 0.0, ss = 0.0;
    if (b < 40) {             // edges: 1e6 elements in 40 chunks of 25000
        int base = b * 25000;
        for (int i = base + t; i < base + 25000; i += 320) {
            float f = e[i];
            s += (double)f; ss += (double)f * f;
        }
    } else {                  // nodes: 320000 elements in 16 chunks of 20000
        int base = (b - 40) * 20000;
        for (int i = base + t; i < base + 20000; i += 320) {
            float f = x[i];
            s += (double)f; ss += (double)f * f;
        }
    }
    s_sh[t] = s; ss_sh[t] = ss;
    __syncthreads();
    if (b < 40) {
        if (t < 10) {
            double a = 0.0, c = 0.0;
            for (int k = t; k < 320; k += 10) { a += s_sh[k]; c += ss_sh[k]; }
            atomicAdd(&g_dsum[t], a);
            atomicAdd(&g_dss[t], c);
        }
    } else {
        if (t < 16) {
            double a = 0.0, c = 0.0;
            for (int k = t; k < 320; k += 16) { a += s_sh[k]; c += ss_sh[k]; }
            atomicAdd(&g_dsum[10 + t], a);
            atomicAdd(&g_dss[10 + t], c);
        }
    }
}

__global__ void bn_fin() {
    int t = threadIdx.x;
    if (t < 10) {
        double m = g_dsum[t] / NE;
        double var = g_dss[t] / NE - m * m;
        g_emean[t] = (float)m;
        g_ers[t] = (float)(1.0 / sqrt(var + 1e-5));
    } else if (t < 26) {
        double m = g_dsum[t] / NN;
        double var = g_dss[t] / NN - m * m;
        g_xmean[t - 10] = (float)m;
        g_xrs[t - 10] = (float)(1.0 / sqrt(var + 1e-5));
    }
}

// ---------------- weight prep ------------------------------------------------
__global__ void prep_w(const float* __restrict__ w1g, const float* __restrict__ w2g,
                       const float* __restrict__ mw1) {
    int b = blockIdx.x;
    if (b < 32) {  // conv1: nn1_w2 [16,512] -> bf16 hi/lo [n512][k16]
        int idx = b * 256 + threadIdx.x;  // 8192
        int n = idx >> 4, k = idx & 15;
        float f = w1g[k * 512 + n];
        __nv_bfloat16 bh = __float2bfloat16(f);
        g_C1h[idx] = bh;
        g_C1l[idx] = __float2bfloat16(f - __bfloat162float(bh));
    } else if (b < 288) {  // conv2: [k32][n2048] -> bf16 hi/lo [n][k]
        int idx = (b - 32) * 256 + threadIdx.x;  // 65536
        int k = idx & 31, n = idx >> 5;
        float f = w2g[k * 2048 + n];
        __nv_bfloat16 bh = __float2bfloat16(f);
        __nv_bfloat16 bl = __float2bfloat16(f - __bfloat162float(bh));
        g_B2h[n * 32 + k] = bh;
        g_B2l[n * 32 + k] = bl;
    } else {  // mlp_w1 [138,64] -> bf16 hi/lo [n64][k152 pad-zero]
        int idx = (b - 288) * 256 + threadIdx.x;  // 9728
        int n = idx / 152, k = idx - n * 152;
        float f = (k < 138) ? mw1[k * 64 + n] : 0.f;
        __nv_bfloat16 bh = __float2bfloat16(f);
        g_W1h[idx] = bh;
        g_W1l[idx] = __float2bfloat16(f - __bfloat162float(bh));
    }
}

// ---------------- K1: edge BN + h1 + h2 (coalesced staging) ------------------
__global__ void k1_edge(const float* __restrict__ e,
                        const float* __restrict__ eg, const float* __restrict__ eb,
                        const float* __restrict__ w1, const float* __restrict__ b1,
                        const float* __restrict__ w2, const float* __restrict__ b2) {
    __shared__ float sw1[160], sw2[320], sb1[16], sb2[32], sg[10], sb[10], sm[10], srs[10];
    __shared__ float in_sh[2560];
    int tid = threadIdx.x;
    int base = blockIdx.x * 2560;
    for (int i = tid; i < 160; i += 256) sw1[i] = w1[i];
    for (int i = tid; i < 320; i += 256) sw2[i] = w2[i];
    if (tid < 16) sb1[tid] = b1[tid];
    if (tid < 32) sb2[tid] = b2[tid];
    if (tid < 10) { sg[tid] = eg[tid]; sb[tid] = eb[tid]; sm[tid] = g_emean[tid]; srs[tid] = g_ers[tid]; }
    for (int i = tid; i < 2560; i += 256) {
        int gi = base + i;
        in_sh[i] = (gi < NE * 10) ? e[gi] : 0.f;
    }
    __syncthreads();
    int eid = blockIdx.x * 256 + tid;
    float ev[10];
    if (eid < NE) {
#pragma unroll
        for (int c = 0; c < 10; c++) {
            float f = (in_sh[tid * 10 + c] - sm[c]) * srs[c] * sg[c] + sb[c];
            ev[c] = f;
        }
#pragma unroll
        for (int o = 0; o < 16; o++) {
            float t = sb1[o];
#pragma unroll
            for (int c = 0; c < 10; c++) t += ev[c] * sw1[c * 16 + o];
            g_h1[eid * 16 + o] = lrelu(t);
        }
#pragma unroll
        for (int o = 0; o < 32; o++) {
            float t = sb2[o];
#pragma unroll
            for (int c = 0; c < 10; c++) t += ev[c] * sw2[c * 32 + o];
            g_h2[eid * 32 + o] = lrelu(t);
        }
    }
    __syncthreads();
    if (eid < NE) {
#pragma unroll
        for (int c = 0; c < 10; c++) in_sh[tid * 10 + c] = ev[c];
    }
    __syncthreads();
    for (int i = tid; i < 2560; i += 256) {
        int gi = base + i;
        if (gi < NE * 10) g_ebn[gi] = in_sh[i];
    }
}

// ---------------- K2: node BN + x1 = xbn @ l1_root + l1_bias -----------------
__global__ void k2_node(const float* __restrict__ x,
                        const float* __restrict__ ng, const float* __restrict__ nb,
                        const float* __restrict__ root, const float* __restrict__ bias) {
    __shared__ float sroot[512], sbias[32], sg[16], sb[16], sm[16], srs[16];
    int tid = threadIdx.x;
    for (int i = tid; i < 512; i += 256) sroot[i] = root[i];
    if (tid < 32) sbias[tid] = bias[tid];
    if (tid < 16) { sg[tid] = ng[tid]; sb[tid] = nb[tid]; sm[tid] = g_xmean[tid]; srs[tid] = g_xrs[tid]; }
    __syncthreads();
    int nid = blockIdx.x * 256 + tid;
    if (nid >= NN) return;
    float xv[16];
#pragma unroll
    for (int i = 0; i < 16; i++) {
        float f = (x[nid * 16 + i] - sm[i]) * srs[i] * sg[i] + sb[i];
        xv[i] = f;
        g_xbn[nid * 16 + i] = f;
    }
#pragma unroll
    for (int o = 0; o < 32; o++) {
        float t = sbias[o];
#pragma unroll
        for (int i = 0; i < 16; i++) t += xv[i] * sroot[i * 32 + o];
        g_x1[nid * 32 + o] = t;
    }
}

// ---------------- K3: NNConv1 via warp MMA (bf16 3-split) --------------------
// 64 edges/block, 128 thr (4 warps x 16 edges). GEMM h1[64,16] x w2[16,512].
// Full B (32KB hi+lo) resident in smem; K=16 = one MMA k-step.
__global__ __launch_bounds__(128) void k3_mma(const int* __restrict__ ei,
                                              const float* __restrict__ b2) {
    __shared__ __nv_bfloat16 Bh[512 * 16], Bl[512 * 16];  // [n][k]
    __shared__ __nv_bfloat16 Ah[64 * 24], Al[64 * 24];    // [e][k] pad 24
    __shared__ float x_sh[64 * 17];                       // [e][i] pad 17
    __shared__ float bias_sh[512];
    __shared__ int dst_sh[64];
    int tid = threadIdx.x;
    int lane = tid & 31, w = tid >> 5;
    int e0 = blockIdx.x * 64;

    {   // copy B (layout identical to global)
        const uint4* sH = (const uint4*)g_C1h;
        const uint4* sL = (const uint4*)g_C1l;
        uint4* dH = (uint4*)Bh;
        uint4* dL = (uint4*)Bl;
        for (int i = tid; i < 1024; i += 128) { dH[i] = sH[i]; dL[i] = sL[i]; }
    }
    for (int i = tid; i < 512; i += 128) bias_sh[i] = b2[i];
    if (tid < 64) {
        int ge = e0 + tid;
        dst_sh[tid] = (ge < NE) ? ei[NE + ge] : 0;
    }
    for (int i = tid; i < 1024; i += 128) {   // A: h1 tile bf16 split
        int e = i >> 4, k = i & 15;
        int ge = e0 + e;
        float f = (ge < NE) ? g_h1[ge * 16 + k] : 0.f;
        __nv_bfloat16 bh = __float2bfloat16(f);
        Ah[e * 24 + k] = bh;
        Al[e * 24 + k] = __float2bfloat16(f - __bfloat162float(bh));
    }
    for (int i = tid; i < 1024; i += 128) {   // x: xbn[src]
        int e = i >> 4, ii = i & 15;
        int ge = e0 + e;
        x_sh[e * 17 + ii] = (ge < NE) ? g_xbn[ei[ge] * 16 + ii] : 0.f;
    }
    __syncthreads();

    int g = lane >> 2, m = lane & 3;
    int eA = w * 16 + g;
    uint32_t a0 = *(const uint32_t*)&Ah[eA * 24 + 2 * m];
    uint32_t a1 = *(const uint32_t*)&Ah[(eA + 8) * 24 + 2 * m];
    uint32_t a2 = *(const uint32_t*)&Ah[eA * 24 + 2 * m + 8];
    uint32_t a3 = *(const uint32_t*)&Ah[(eA + 8) * 24 + 2 * m + 8];
    uint32_t l0 = *(const uint32_t*)&Al[eA * 24 + 2 * m];
    uint32_t l1 = *(const uint32_t*)&Al[(eA + 8) * 24 + 2 * m];
    uint32_t l2 = *(const uint32_t*)&Al[eA * 24 + 2 * m + 8];
    uint32_t l3 = *(const uint32_t*)&Al[(eA + 8) * 24 + 2 * m + 8];

    float acc[16];
#pragma unroll
    for (int i = 0; i < 16; i++) acc[i] = 0.f;

#pragma unroll 4
    for (int ob = 0; ob < 64; ob++) {
        const __nv_bfloat16* bp = &Bh[(ob * 8 + g) * 16];
        const __nv_bfloat16* lp = &Bl[(ob * 8 + g) * 16];
        uint32_t b0 = *(const uint32_t*)&bp[2 * m];
        uint32_t b1 = *(const uint32_t*)&bp[2 * m + 8];
        uint32_t bl0 = *(const uint32_t*)&lp[2 * m];
        uint32_t bl1 = *(const uint32_t*)&lp[2 * m + 8];

        float c0 = 0.f, c1 = 0.f, c2 = 0.f, c3 = 0.f;
        mma_bf16(c0, c1, c2, c3, a0, a1, a2, a3, b0, b1);
        mma_bf16(c0, c1, c2, c3, l0, l1, l2, l3, b0, b1);
        mma_bf16(c0, c1, c2, c3, a0, a1, a2, a3, bl0, bl1);

        int iL = ob >> 2;                 // n = ob*8+col; i = n>>5
        float xa = x_sh[eA * 17 + iL];
        float xb = x_sh[(eA + 8) * 17 + iL];
        float bv0 = bias_sh[ob * 8 + 2 * m];
        float bv1 = bias_sh[ob * 8 + 2 * m + 1];
        int q = (ob & 3) * 2;
        acc[q]         = fmaf(xa, lrelu(c0 + bv0), acc[q]);
        acc[q + 1]     = fmaf(xa, lrelu(c1 + bv1), acc[q + 1]);
        acc[8 + q]     = fmaf(xb, lrelu(c2 + bv0), acc[8 + q]);
        acc[8 + q + 1] = fmaf(xb, lrelu(c3 + bv1), acc[8 + q + 1]);
    }

    int o0 = 2 * m;
    if (e0 + eA < NE) {
        int d = dst_sh[eA];
#pragma unroll
        for (int q = 0; q < 4; q++) {
            atomicAdd(&g_x1[d * 32 + q * 8 + o0], acc[q * 2]);
            atomicAdd(&g_x1[d * 32 + q * 8 + o0 + 1], acc[q * 2 + 1]);
        }
    }
    if (e0 + eA + 8 < NE) {
        int d = dst_sh[eA + 8];
#pragma unroll
        for (int q = 0; q < 4; q++) {
            atomicAdd(&g_x1[d * 32 + q * 8 + o0], acc[8 + q * 2]);
            atomicAdd(&g_x1[d * 32 + q * 8 + o0 + 1], acc[8 + q * 2 + 1]);
        }
    }
}

// ---------------- K4: x2 = x1 @ l2_root + l2_bias ----------------------------
__global__ void k4_node(const float* __restrict__ root, const float* __restrict__ bias) {
    __shared__ float sroot[2048], sbias[64];
    int tid = threadIdx.x;
    for (int i = tid; i < 2048; i += 256) sroot[i] = root[i];
    if (tid < 64) sbias[tid] = bias[tid];
    __syncthreads();
    int idx = blockIdx.x * 256 + tid;
    if (idx >= NN * 64) return;
    int n = idx >> 6, o = idx & 63;
    float t = sbias[o];
#pragma unroll
    for (int i = 0; i < 32; i++) t += g_x1[n * 32 + i] * sroot[i * 64 + o];
    g_x2[idx] = t;
}

// ---------------- K5: NNConv2 via warp MMA (bf16 3-split, reg dbl-buffer) ----
__global__ __launch_bounds__(128) void k5_conv2_mma(const int* __restrict__ ei,
                                                    const float* __restrict__ b2) {
    __shared__ __nv_bfloat16 Bh_sh[128 * 40];   // [n][k] pad 40
    __shared__ __nv_bfloat16 Bl_sh[128 * 40];
    __shared__ __nv_bfloat16 Ah_sh[64 * 40];    // [e][k] pad 40
    __shared__ __nv_bfloat16 Al_sh[64 * 40];
    __shared__ float x_sh[64 * 33];             // [e][i] pad 33
    __shared__ float bias_sh[2048];
    __shared__ int dst_sh[64];
    int tid = threadIdx.x;
    int lane = tid & 31, w = tid >> 5;
    int e0 = blockIdx.x * 64;

    uint4 rH[4], rL[4];
    int n_ = tid >> 2, q_ = tid & 3;
    {
        const uint4* srcH = (const uint4*)(g_B2h);
        const uint4* srcL = (const uint4*)(g_B2l);
#pragma unroll
        for (int j = 0; j < 4; j++) {
            rH[j] = srcH[(n_ + 32 * j) * 4 + q_];
            rL[j] = srcL[(n_ + 32 * j) * 4 + q_];
        }
    }

    for (int i = tid; i < 2048; i += 128) {
        int e = i >> 5, k = i & 31;
        int ge = e0 + e;
        float f = (ge < NE) ? g_h2[ge * 32 + k] : 0.f;
        __nv_bfloat16 bh = __float2bfloat16(f);
        Ah_sh[e * 40 + k] = bh;
        Al_sh[e * 40 + k] = __float2bfloat16(f - __bfloat162float(bh));
    }
    for (int i = tid; i < 2048; i += 128) {
        int e = i >> 5, ii = i & 31;
        int ge = e0 + e;
        x_sh[e * 33 + ii] = (ge < NE) ? g_x1[ei[ge] * 32 + ii] : 0.f;
    }
    if (tid < 64) {
        int ge = e0 + tid;
        dst_sh[tid] = (ge < NE) ? ei[NE + ge] : 0;
    }
    for (int i = tid; i < 2048; i += 128) bias_sh[i] = b2[i];
    __syncthreads();

    int g = lane >> 2, m = lane & 3;
    int eA = w * 16 + g;
    uint32_t ah[2][4], al[2][4];
#pragma unroll
    for (int ks = 0; ks < 2; ks++) {
        int kb = ks * 16 + 2 * m;
        ah[ks][0] = *(const uint32_t*)&Ah_sh[eA * 40 + kb];
        ah[ks][1] = *(const uint32_t*)&Ah_sh[(eA + 8) * 40 + kb];
        ah[ks][2] = *(const uint32_t*)&Ah_sh[eA * 40 + kb + 8];
        ah[ks][3] = *(const uint32_t*)&Ah_sh[(eA + 8) * 40 + kb + 8];
        al[ks][0] = *(const uint32_t*)&Al_sh[eA * 40 + kb];
        al[ks][1] = *(const uint32_t*)&Al_sh[(eA + 8) * 40 + kb];
        al[ks][2] = *(const uint32_t*)&Al_sh[eA * 40 + kb + 8];
        al[ks][3] = *(const uint32_t*)&Al_sh[(eA + 8) * 40 + kb + 8];
    }

    float acc[32];
#pragma unroll
    for (int i = 0; i < 32; i++) acc[i] = 0.f;

    for (int c = 0; c < 16; c++) {
        if (c > 0) __syncthreads();
#pragma unroll
        for (int j = 0; j < 4; j++) {
            *((uint4*)((char*)Bh_sh + (n_ + 32 * j) * 80) + q_) = rH[j];
            *((uint4*)((char*)Bl_sh + (n_ + 32 * j) * 80) + q_) = rL[j];
        }
        __syncthreads();
        if (c + 1 < 16) {
            const uint4* srcH = (const uint4*)(g_B2h + (size_t)(c + 1) * 4096);
            const uint4* srcL = (const uint4*)(g_B2l + (size_t)(c + 1) * 4096);
#pragma unroll
            for (int j = 0; j < 4; j++) {
                rH[j] = srcH[(n_ + 32 * j) * 4 + q_];
                rL[j] = srcL[(n_ + 32 * j) * 4 + q_];
            }
        }

#pragma unroll 2
        for (int ob = 0; ob < 16; ob++) {
            const __nv_bfloat16* bhp = &Bh_sh[(ob * 8 + g) * 40];
            const __nv_bfloat16* blp = &Bl_sh[(ob * 8 + g) * 40];
            uint32_t bh00 = *(const uint32_t*)&bhp[2 * m];
            uint32_t bh01 = *(const uint32_t*)&bhp[2 * m + 8];
            uint32_t bh10 = *(const uint32_t*)&bhp[2 * m + 16];
            uint32_t bh11 = *(const uint32_t*)&bhp[2 * m + 24];
            uint32_t bl00 = *(const uint32_t*)&blp[2 * m];
            uint32_t bl01 = *(const uint32_t*)&blp[2 * m + 8];
            uint32_t bl10 = *(const uint32_t*)&blp[2 * m + 16];
            uint32_t bl11 = *(const uint32_t*)&blp[2 * m + 24];

            float cA0 = 0.f, cA1 = 0.f, cA2 = 0.f, cA3 = 0.f;
            float cB0 = 0.f, cB1 = 0.f, cB2 = 0.f, cB3 = 0.f;
            mma_bf16(cA0, cA1, cA2, cA3, ah[0][0], ah[0][1], ah[0][2], ah[0][3], bh00, bh01);
            mma_bf16(cA0, cA1, cA2, cA3, al[0][0], al[0][1], al[0][2], al[0][3], bh00, bh01);
            mma_bf16(cA0, cA1, cA2, cA3, ah[0][0], ah[0][1], ah[0][2], ah[0][3], bl00, bl01);
            mma_bf16(cB0, cB1, cB2, cB3, ah[1][0], ah[1][1], ah[1][2], ah[1][3], bh10, bh11);
            mma_bf16(cB0, cB1, cB2, cB3, al[1][0], al[1][1], al[1][2], al[1][3], bh10, bh11);
            mma_bf16(cB0, cB1, cB2, cB3, ah[1][0], ah[1][1], ah[1][2], ah[1][3], bl10, bl11);

            int iL = 2 * c + (ob >> 3);
            float xa = x_sh[eA * 33 + iL];
            float xb = x_sh[(eA + 8) * 33 + iL];
            int nb = c * 128 + ob * 8 + 2 * m;
            float bv0 = bias_sh[nb], bv1 = bias_sh[nb + 1];
            int ai = (ob & 7) * 2;
            acc[ai]          = fmaf(xa, lrelu(cA0 + cB0 + bv0), acc[ai]);
            acc[ai + 1]      = fmaf(xa, lrelu(cA1 + cB1 + bv1), acc[ai + 1]);
            acc[16 + ai]     = fmaf(xb, lrelu(cA2 + cB2 + bv0), acc[16 + ai]);
            acc[16 + ai + 1] = fmaf(xb, lrelu(cA3 + cB3 + bv1), acc[16 + ai + 1]);
        }
    }

    int o0 = 2 * m;
    if (e0 + eA < NE) {
        int d = dst_sh[eA];
#pragma unroll
        for (int ob = 0; ob < 8; ob++) {
            atomicAdd(&g_x2[d * 64 + ob * 8 + o0], acc[ob * 2]);
            atomicAdd(&g_x2[d * 64 + ob * 8 + o0 + 1], acc[ob * 2 + 1]);
        }
    }
    if (e0 + eA + 8 < NE) {
        int d = dst_sh[eA + 8];
#pragma unroll
        for (int ob = 0; ob < 8; ob++) {
            atomicAdd(&g_x2[d * 64 + ob * 8 + o0], acc[16 + ob * 2]);
            atomicAdd(&g_x2[d * 64 + ob * 8 + o0 + 1], acc[16 + ob * 2 + 1]);
        }
    }
}

// ---------------- K6a: edge MLP layer1 via warp MMA (bf16 3-split) -----------
__global__ __launch_bounds__(128) void k6a_mma(const int* __restrict__ ei,
                                               const float* __restrict__ b1) {
    __shared__ __nv_bfloat16 Ah[16 * 152], Al[16 * 152];  // [e][k]
    __shared__ __nv_bfloat16 Bh[64 * 152], Bl[64 * 152];  // [n][k]
    __shared__ float sb1[64];
    __shared__ int se[32];
    int tid = threadIdx.x;
    int e0 = blockIdx.x * 16;

    if (tid < 16) se[tid] = ei[e0 + tid];
    else if (tid < 32) se[tid] = ei[NE + e0 + tid - 16];
    if (tid >= 64 && tid < 128) sb1[tid - 64] = b1[tid - 64];
    {
        const uint4* sH = (const uint4*)g_W1h;
        const uint4* sL = (const uint4*)g_W1l;
        uint4* dH = (uint4*)Bh;
        uint4* dL = (uint4*)Bl;
        for (int i = tid; i < 1216; i += 128) { dH[i] = sH[i]; dL[i] = sL[i]; }
    }
    __syncthreads();

    for (int i = tid; i < 16 * 152; i += 128) {
        int e = i / 152, k = i - e * 152;
        float v = 0.f;
        if (k < 64)       v = g_x2[se[e] * 64 + k];
        else if (k < 128) v = g_x2[se[16 + e] * 64 + (k - 64)];
        else if (k < 138) v = g_ebn[(e0 + e) * 10 + (k - 128)];
        __nv_bfloat16 bh = __float2bfloat16(v);
        Ah[i] = bh;
        Al[i] = __float2bfloat16(v - __bfloat162float(bh));
    }
    __syncthreads();

    int lane = tid & 31, w = tid >> 5, g = lane >> 2, m = lane & 3;
#pragma unroll
    for (int ob = 0; ob < 2; ob++) {
        int n0 = (w * 2 + ob) * 8;
        float c0 = 0.f, c1 = 0.f, c2 = 0.f, c3 = 0.f;
#pragma unroll
        for (int ks = 0; ks < 9; ks++) {
            int kb = ks * 16 + 2 * m;
            uint32_t a0 = *(const uint32_t*)&Ah[g * 152 + kb];
            uint32_t a1 = *(const uint32_t*)&Ah[(g + 8) * 152 + kb];
            uint32_t a2 = *(const uint32_t*)&Ah[g * 152 + kb + 8];
            uint32_t a3 = *(const uint32_t*)&Ah[(g + 8) * 152 + kb + 8];
            uint32_t l0 = *(const uint32_t*)&Al[g * 152 + kb];
            uint32_t l1 = *(const uint32_t*)&Al[(g + 8) * 152 + kb];
            uint32_t l2 = *(const uint32_t*)&Al[g * 152 + kb + 8];
            uint32_t l3 = *(const uint32_t*)&Al[(g + 8) * 152 + kb + 8];
            const __nv_bfloat16* bp = &Bh[(n0 + g) * 152 + ks * 16];
            const __nv_bfloat16* lp = &Bl[(n0 + g) * 152 + ks * 16];
            uint32_t b0 = *(const uint32_t*)&bp[2 * m];
            uint32_t b1r = *(const uint32_t*)&bp[2 * m + 8];
            uint32_t bl0 = *(const uint32_t*)&lp[2 * m];
            uint32_t bl1 = *(const uint32_t*)&lp[2 * m + 8];
            mma_bf16(c0, c1, c2, c3, a0, a1, a2, a3, b0, b1r);
            mma_bf16(c0, c1, c2, c3, l0, l1, l2, l3, b0, b1r);
            mma_bf16(c0, c1, c2, c3, a0, a1, a2, a3, bl0, bl1);
        }
        int col = n0 + 2 * m;
        g_m1[(e0 + g) * 64 + col]         = lrelu(c0 + sb1[col]);
        g_m1[(e0 + g) * 64 + col + 1]     = lrelu(c1 + sb1[col + 1]);
        g_m1[(e0 + g + 8) * 64 + col]     = lrelu(c2 + sb1[col]);
        g_m1[(e0 + g + 8) * 64 + col + 1] = lrelu(c3 + sb1[col + 1]);
    }
}

// ---------------- K6b: edge MLP layers 2-5 -----------------------------------
__global__ __launch_bounds__(256) void k6b_mlp(
    const float* __restrict__ w2, const float* __restrict__ b2,
    const float* __restrict__ w3, const float* __restrict__ b3,
    const float* __restrict__ w4, const float* __restrict__ b4,
    const float* __restrict__ w5, const float* __restrict__ b5,
    float* __restrict__ out) {
    __shared__ float sw2[2048], sw3[512], sw4[128], sw5[16];
    __shared__ float sb2[32], sb3[16], sb4[8], sb5[2];
    __shared__ __align__(16) float h1_sh[64 * 36];
    __shared__ __align__(16) float h2_sh[32 * 36];
    int tid = threadIdx.x;
    int e0 = blockIdx.x * 32;

    for (int i = tid; i < 2048; i += 256) sw2[i] = w2[i];
    for (int i = tid; i < 512; i += 256) sw3[i] = w3[i];
    if (tid < 128) sw4[tid] = w4[tid];
    if (tid < 16) sw5[tid] = w5[tid];
    if (tid < 32) sb2[tid] = b2[tid];
    if (tid < 16) sb3[tid] = b3[tid];
    if (tid < 8) sb4[tid] = b4[tid];
    if (tid < 2) sb5[tid] = b5[tid];
    for (int i = tid; i < 2048; i += 256) {       // coalesced: k-major
        int k = i & 63, e = i >> 6;
        h1_sh[k * 36 + e] = g_m1[(e0 + e) * 64 + k];
    }
    __syncthreads();

    {
        int o = tid & 31, g = tid >> 5;
        ull a0 = bcast2(sb2[o]);
        ull a1 = a0;
#pragma unroll 4
        for (int k = 0; k < 64; k++) {
            ull wb = bcast2(sw2[k * 32 + o]);
            ulonglong2 h = *(const ulonglong2*)&h1_sh[k * 36 + g * 4];
            a0 = fma2(h.x, wb, a0);
            a1 = fma2(h.y, wb, a1);
        }
        float2 v0 = unpk2(a0), v1 = unpk2(a1);
        h2_sh[o * 36 + g * 4 + 0] = lrelu(v0.x);
        h2_sh[o * 36 + g * 4 + 1] = lrelu(v0.y);
        h2_sh[o * 36 + g * 4 + 2] = lrelu(v1.x);
        h2_sh[o * 36 + g * 4 + 3] = lrelu(v1.y);
    }
    __syncthreads();

    if (tid < 32) {
        int e = tid, ge = e0 + e;
        float h2r[32];
#pragma unroll
        for (int k = 0; k < 32; k++) h2r[k] = h2_sh[k * 36 + e];
        float h3[16];
#pragma unroll
        for (int o = 0; o < 16; o++) {
            float a = sb3[o];
#pragma unroll
            for (int k = 0; k < 32; k++) a += h2r[k] * sw3[k * 16 + o];
            h3[o] = lrelu(a);
        }
        float h4[8];
#pragma unroll
        for (int o = 0; o < 8; o++) {
            float a = sb4[o];
#pragma unroll
            for (int k = 0; k < 16; k++) a += h3[k] * sw4[k * 8 + o];
            h4[o] = lrelu(a);
        }
#pragma unroll
        for (int o = 0; o < 2; o++) {
            float a = sb5[o];
#pragma unroll
            for (int k = 0; k < 8; k++) a += h4[k] * sw5[k * 2 + o];
            out[(size_t)ge * 2 + o] = a;
        }
    }
}

// ---------------- launch -----------------------------------------------------
extern "C" void kernel_launch(void* const* d_in, const int* in_sizes, int n_in,
                              void* d_out, int out_size) {
    const float* x = (const float*)d_in[0];
    const float* e = (const float*)d_in[1];
    const int* ei = (const int*)d_in[2];     // edge_index: int32
    const float* bn_node_g = (const float*)d_in[4];
    const float* bn_node_b = (const float*)d_in[5];
    const float* bn_edge_g = (const float*)d_in[6];
    const float* bn_edge_b = (const float*)d_in[7];
    const float* nn1_w1 = (const float*)d_in[8];
    const float* nn1_b1 = (const float*)d_in[9];
    const float* nn1_w2 = (const float*)d_in[10];
    const float* nn1_b2 = (const float*)d_in[11];
    const float* nn2_w1 = (const float*)d_in[12];
    const float* nn2_b1 = (const float*)d_in[13];
    const float* nn2_w2 = (const float*)d_in[14];
    const float* nn2_b2 = (const float*)d_in[15];
    const float* l1_root = (const float*)d_in[16];
    const float* l1_bias = (const float*)d_in[17];
    const float* l2_root = (const float*)d_in[18];
    const float* l2_bias = (const float*)d_in[19];
    const float* mlp_w1 = (const float*)d_in[20];
    const float* mlp_b1 = (const float*)d_in[21];
    const float* mlp_w2 = (const float*)d_in[22];
    const float* mlp_b2 = (const float*)d_in[23];
    const float* mlp_w3 = (const float*)d_in[24];
    const float* mlp_b3 = (const float*)d_in[25];
    const float* mlp_w4 = (const float*)d_in[26];
    const float* mlp_b4 = (const float*)d_in[27];
    const float* mlp_w5 = (const float*)d_in[28];
    const float* mlp_b5 = (const float*)d_in[29];
    float* out = (float*)d_out;

    bn_init<<<1, 32>>>();
    bn_acc<<<56, 320>>>(e, x);
    bn_fin<<<1, 32>>>();
    prep_w<<<326, 256>>>(nn1_w2, nn2_w2, mlp_w1);
    k1_edge<<<(NE + 255) / 256, 256>>>(e, bn_edge_g, bn_edge_b, nn1_w1, nn1_b1, nn2_w1, nn2_b1);
    k2_node<<<(NN + 255) / 256, 256>>>(x, bn_node_g, bn_node_b, l1_root, l1_bias);
    k3_mma<<<(NE + 63) / 64, 128>>>(ei, nn1_b2);
    k4_node<<<(NN * 64 + 255) / 256, 256>>>(l2_root, l2_bias);
    k5_conv2_mma<<<(NE + 63) / 64, 128>>>(ei, nn2_b2);
    k6a_mma<<<NE / 16, 128>>>(ei, mlp_b1);
    k6b_mlp<<<NE / 32, 256>>>(mlp_w2, mlp_b2, mlp_w3, mlp_b3,
                              mlp_w4, mlp_b4, mlp_w5, mlp_b5, out);
}